// round 12
// baseline (speedup 1.0000x reference)
#include <cuda_runtime.h>
#include <cuda_bf16.h>
#include <cuda_fp16.h>
#include <math.h>
#include <stdint.h>

#define NN   50000
#define NE   800000
#define DIN  128
#define DH   256
#define DOUT 64
#define NG   500
#define NEG  0.01f
#define EPSN 1e-12f
#define NB   ((NN + 255) / 256)   // 196 scan blocks

// ---------------- scratch ----------------------------------------------------
__device__ int    g_deg[NN];
__device__ int    g_rps[NN];      // block-local exclusive scan of deg
__device__ int    g_boff[NB];     // exclusive scan of block sums
__device__ int    g_bsum[NB];
__device__ int    g_done;
__device__ int    g_rank[NE];
__device__ int    g_csr[NE];
__device__ int    g_mark[NN];
__device__ int    g_mlist[NN];
__device__ int    g_mcount;
__device__ __half g_xh[(size_t)NN * DIN];        // fp16 copy of x for gather
__device__ float  g_agg1[(size_t)NN * DIN];
__device__ float  g_h1[(size_t)NN * DH];
__device__ float  g_agg2[(size_t)NN * DH];       // compacted rows [mcount]
__device__ float  g_h2[(size_t)NN * DH];
// split weights, transposed [n][k] (col-major B for mma .row.col)
__device__ __nv_bfloat16 g_B1hi[DH * DIN];
__device__ __nv_bfloat16 g_B1lo[DH * DIN];
__device__ __nv_bfloat16 g_B2hi[DH * DH];
__device__ __nv_bfloat16 g_B2lo[DH * DH];

__device__ __forceinline__ float lrelu(float t) { return t >= 0.f ? t : NEG * t; }

__device__ __forceinline__ uint32_t smem_u32(const void* p) {
    uint32_t a;
    asm("{ .reg .u64 t; cvta.to.shared.u64 t, %1; cvt.u32.u64 %0, t; }" : "=r"(a) : "l"(p));
    return a;
}
__device__ __forceinline__ void mma16816(float* d, const uint32_t* a,
                                         uint32_t b0, uint32_t b1) {
    asm volatile(
        "mma.sync.aligned.m16n8k16.row.col.f32.bf16.bf16.f32 "
        "{%0,%1,%2,%3}, {%4,%5,%6,%7}, {%8,%9}, {%0,%1,%2,%3};"
        : "+f"(d[0]), "+f"(d[1]), "+f"(d[2]), "+f"(d[3])
        : "r"(a[0]), "r"(a[1]), "r"(a[2]), "r"(a[3]), "r"(b0), "r"(b1));
}
__device__ __forceinline__ void ldsm4(uint32_t* r, uint32_t addr) {
    asm volatile("ldmatrix.sync.aligned.m8n8.x4.shared.b16 {%0,%1,%2,%3}, [%4];"
                 : "=r"(r[0]), "=r"(r[1]), "=r"(r[2]), "=r"(r[3]) : "r"(addr));
}
__device__ __forceinline__ int seg_beg(int v) {
    return g_rps[v] + g_boff[v >> 8];
}

// ---------------- preprocessing ----------------------------------------------
// count (stores per-edge rank) + mark + weight split + fp16 x conversion
__global__ void k_count_prep(const int* __restrict__ ei,
                             const float* __restrict__ x,
                             const float* __restrict__ W1,
                             const float* __restrict__ W2) {
    int t = blockIdx.x * blockDim.x + threadIdx.x;
    {   // fp16 conversion: 8 elements per thread, covers all 6.4M exactly
        size_t c0 = (size_t)t * 8;
        if (c0 < (size_t)NN * DIN) {
            float4 a = __ldg((const float4*)&x[c0]);
            float4 b = __ldg((const float4*)&x[c0 + 4]);
            __half2 h0 = __floats2half2_rn(a.x, a.y);
            __half2 h1 = __floats2half2_rn(a.z, a.w);
            __half2 h2 = __floats2half2_rn(b.x, b.y);
            __half2 h3 = __floats2half2_rn(b.z, b.w);
            *(uint4*)&g_xh[c0] = make_uint4(*(uint32_t*)&h0, *(uint32_t*)&h1,
                                            *(uint32_t*)&h2, *(uint32_t*)&h3);
        }
    }
    int e0 = t * 4;
    if (e0 < NE) {
        int4 s4 = *(const int4*)&ei[e0];
        int4 d4 = *(const int4*)&ei[NE + e0];
        int r0 = atomicAdd(&g_deg[d4.x], 1);
        int r1 = atomicAdd(&g_deg[d4.y], 1);
        int r2 = atomicAdd(&g_deg[d4.z], 1);
        int r3 = atomicAdd(&g_deg[d4.w], 1);
        *(int4*)&g_rank[e0] = make_int4(r0, r1, r2, r3);
        if (d4.x % 100 == 0) g_mark[s4.x] = 1;
        if (d4.y % 100 == 0) g_mark[s4.y] = 1;
        if (d4.z % 100 == 0) g_mark[s4.z] = 1;
        if (d4.w % 100 == 0) g_mark[s4.w] = 1;
    }
    if (t < DIN * DH) {           // W1: [k][n]
        int k = t / DH, n = t % DH;
        float f = W1[t];
        __nv_bfloat16 h = __float2bfloat16(f);
        g_B1hi[n * DIN + k] = h;
        g_B1lo[n * DIN + k] = __float2bfloat16(f - __bfloat162float(h));
    }
    if (t < DH * DH) {            // W2: [k][n]
        int k = t / DH, n = t % DH;
        float f = W2[t];
        __nv_bfloat16 h = __float2bfloat16(f);
        g_B2hi[n * DH + k] = h;
        g_B2lo[n * DH + k] = __float2bfloat16(f - __bfloat162float(h));
    }
}

__device__ __forceinline__ int block_scan_inc(int v, int tid, int* ws) {
    int lane = tid & 31, wd = tid >> 5;
    int x = v;
    #pragma unroll
    for (int o = 1; o < 32; o <<= 1) {
        int t = __shfl_up_sync(0xffffffffu, x, o);
        if (lane >= o) x += t;
    }
    if (lane == 31) ws[wd] = x;
    __syncthreads();
    if (tid < 8) {
        int s = ws[tid];
        #pragma unroll
        for (int o = 1; o < 8; o <<= 1) {
            int t = __shfl_up_sync(0xffu, s, o);
            if (tid >= o) s += t;
        }
        ws[tid] = s;
    }
    __syncthreads();
    return x + (wd ? ws[wd - 1] : 0);
}

// single-kernel scan: block-local scans + last-block scans the block sums;
// also compacts marked nodes.
__global__ void k_scan() {
    __shared__ int ws[8];
    __shared__ int s_last;
    int tid = threadIdx.x, bid = blockIdx.x;
    int gi = bid * 256 + tid;
    int v = (gi < NN) ? g_deg[gi] : 0;
    int inc = block_scan_inc(v, tid, ws);
    if (gi < NN) {
        g_rps[gi] = inc - v;              // block-local exclusive
        if (g_mark[gi]) {
            int p = atomicAdd(&g_mcount, 1);
            g_mlist[p] = gi;
        }
    }
    if (tid == 255) g_bsum[bid] = inc;    // block total
    __threadfence();
    __syncthreads();
    if (tid == 0) {
        int ticket = atomicAdd(&g_done, 1);
        s_last = (ticket == NB - 1);
    }
    __syncthreads();
    if (s_last) {
        __shared__ int ws2[8];
        int v2 = (tid < NB) ? g_bsum[tid] : 0;
        int inc2 = block_scan_inc(v2, tid, ws2);
        if (tid < NB) g_boff[tid] = inc2 - v2;   // exclusive
    }
}

// atomic-free scatter: position = seg_beg(dst) + precomputed rank
__global__ void k_fill(const int* __restrict__ ei) {
    int t = blockIdx.x * blockDim.x + threadIdx.x;
    int e0 = t * 4;
    if (e0 >= NE) return;
    int4 s4 = *(const int4*)&ei[e0];
    int4 d4 = *(const int4*)&ei[NE + e0];
    int4 r4 = *(const int4*)&g_rank[e0];
    g_csr[seg_beg(d4.x) + r4.x] = s4.x;
    g_csr[seg_beg(d4.y) + r4.y] = s4.y;
    g_csr[seg_beg(d4.z) + r4.z] = s4.z;
    g_csr[seg_beg(d4.w) + r4.w] = s4.w;
}

// ---------------- aggregation (warp per node, fp16 gather, fp32 accumulate) ---
__global__ void k_agg1() {
    int w    = (blockIdx.x * blockDim.x + threadIdx.x) >> 5;
    int lane = threadIdx.x & 31;
    if (w >= NN) return;
    int beg = seg_beg(w), end = beg + g_deg[w];
    float4 acc = make_float4(0.f, 0.f, 0.f, 0.f);
    int j = beg;
    for (; j + 4 <= end; j += 4) {
        int s0 = g_csr[j], s1 = g_csr[j + 1], s2 = g_csr[j + 2], s3 = g_csr[j + 3];
        uint2 u0 = __ldg((const uint2*)&g_xh[(size_t)s0 * DIN + lane * 4]);
        uint2 u1 = __ldg((const uint2*)&g_xh[(size_t)s1 * DIN + lane * 4]);
        uint2 u2 = __ldg((const uint2*)&g_xh[(size_t)s2 * DIN + lane * 4]);
        uint2 u3 = __ldg((const uint2*)&g_xh[(size_t)s3 * DIN + lane * 4]);
        float2 a0 = __half22float2(*(__half2*)&u0.x), b0 = __half22float2(*(__half2*)&u0.y);
        float2 a1 = __half22float2(*(__half2*)&u1.x), b1 = __half22float2(*(__half2*)&u1.y);
        float2 a2 = __half22float2(*(__half2*)&u2.x), b2 = __half22float2(*(__half2*)&u2.y);
        float2 a3 = __half22float2(*(__half2*)&u3.x), b3 = __half22float2(*(__half2*)&u3.y);
        acc.x += a0.x + a1.x + a2.x + a3.x;
        acc.y += a0.y + a1.y + a2.y + a3.y;
        acc.z += b0.x + b1.x + b2.x + b3.x;
        acc.w += b0.y + b1.y + b2.y + b3.y;
    }
    for (; j < end; j++) {
        int s = g_csr[j];
        uint2 u = __ldg((const uint2*)&g_xh[(size_t)s * DIN + lane * 4]);
        float2 a = __half22float2(*(__half2*)&u.x), b = __half22float2(*(__half2*)&u.y);
        acc.x += a.x; acc.y += a.y; acc.z += b.x; acc.w += b.y;
    }
    *(float4*)&g_agg1[(size_t)w * DIN + lane * 4] = acc;
}

// agg2 writes COMPACTED rows (row w = position in mlist)
__global__ void k_agg2() {
    int w    = (blockIdx.x * blockDim.x + threadIdx.x) >> 5;
    int lane = threadIdx.x & 31;
    if (w >= g_mcount) return;
    int v   = g_mlist[w];
    int beg = seg_beg(v), end = beg + g_deg[v];
    float4 a0 = make_float4(0.f, 0.f, 0.f, 0.f);
    float4 a1 = make_float4(0.f, 0.f, 0.f, 0.f);
    for (int j = beg; j < end; j++) {
        int s = g_csr[j];
        const float* r = &g_h1[(size_t)s * DH];
        float4 v0 = *(const float4*)&r[lane * 4];
        float4 v1 = *(const float4*)&r[128 + lane * 4];
        a0.x += v0.x; a0.y += v0.y; a0.z += v0.z; a0.w += v0.w;
        a1.x += v1.x; a1.y += v1.y; a1.z += v1.z; a1.w += v1.w;
    }
    float* o = &g_agg2[(size_t)w * DH];
    *(float4*)&o[lane * 4]       = a0;
    *(float4*)&o[128 + lane * 4] = a1;
}

// ---------------- mma.sync split-bf16 GEMM + fused bias/L2norm/leakyrelu ------
// 512 threads = 16 warps (2m x 8n), tile 64m x 256n, K chunks of 64 (R8 config).
#define PADK 72
#define SM_AHI  0
#define SM_ALO  (SM_AHI + 64 * PADK * 2)
#define SM_BHI  (SM_ALO + 64 * PADK * 2)
#define SM_BLO  (SM_BHI + 256 * PADK * 2)
#define SM_BIAS (SM_BLO + 256 * PADK * 2)
#define SM_SS   (SM_BIAS + DH * 4)
#define SM_INV  (SM_SS + 64 * 8 * 4)
#define SM_TOT  (SM_INV + 64 * 4)

template <int LAYER>
__global__ void __launch_bounds__(512, 1)
k_gemm_mma(const float* __restrict__ bias) {
    constexpr int K     = (LAYER == 1) ? DIN : DH;
    constexpr int KITER = K / 64;
    extern __shared__ char smem[];
    __nv_bfloat16* Ah = (__nv_bfloat16*)(smem + SM_AHI);
    __nv_bfloat16* Al = (__nv_bfloat16*)(smem + SM_ALO);
    __nv_bfloat16* Bh = (__nv_bfloat16*)(smem + SM_BHI);
    __nv_bfloat16* Bl = (__nv_bfloat16*)(smem + SM_BLO);
    float* bs  = (float*)(smem + SM_BIAS);
    float* ssb = (float*)(smem + SM_SS);
    float* ivb = (float*)(smem + SM_INV);

    int M = (LAYER == 1) ? NN : g_mcount;
    int m0 = blockIdx.x * 64;
    if (m0 >= M) return;

    int tid = threadIdx.x, wid = tid >> 5, lane = tid & 31;
    int gid = lane >> 2, tig = lane & 3;
    int mw = (wid >> 3) * 32;       // 2 m warp-rows
    int nw = wid & 7;               // 8 n warps
    int nbw = nw * 32;

    if (tid < DH) bs[tid] = bias[tid];

    const float* A = (LAYER == 1) ? g_agg1 : g_agg2;
    const __nv_bfloat16* Bhig = (LAYER == 1) ? g_B1hi : g_B2hi;
    const __nv_bfloat16* Blog = (LAYER == 1) ? g_B1lo : g_B2lo;
    float* C = (LAYER == 1) ? g_h1 : g_h2;

    // A staging map: thread -> row tid>>3 (0..63), seg (tid&7)*8
    int  arl    = tid >> 3;
    int  aseg   = (tid & 7) * 8;
    int  agrow  = m0 + arl;
    bool avalid = agrow < M;
    const float* arowp = A + (size_t)(avalid ? agrow : 0) * K;
    // B staging map: thread -> row tid>>1 (0..255), half (tid&1)*32
    int brl  = tid >> 1;
    int bseg = (tid & 1) * 32;

    // ldmatrix lane maps
    uint32_t ah_b = smem_u32(Ah), al_b = smem_u32(Al);
    uint32_t bh_b = smem_u32(Bh), bl_b = smem_u32(Bl);
    int a_row = mw + (lane & 7) + ((lane >> 3) & 1) * 8;   // + mi*16
    int a_kof = (lane >> 4) * 8;
    int b_row = nbw + (lane & 7) + ((lane >> 4) & 1) * 8;  // + nj*16
    int b_kof = ((lane >> 3) & 1) * 8;

    float acc[2][4][4];
    #pragma unroll
    for (int mi = 0; mi < 2; mi++)
        #pragma unroll
        for (int ni = 0; ni < 4; ni++)
            #pragma unroll
            for (int q = 0; q < 4; q++) acc[mi][ni][q] = 0.f;

    for (int it = 0; it < KITER; it++) {
        int k0 = it * 64;
        // ---- stage A: 8 fp32 per thread -> bf16 hi/lo ----
        {
            float4 v = make_float4(0.f, 0.f, 0.f, 0.f), w = v;
            if (avalid) {
                const float* ap = arowp + k0 + aseg;
                v = *(const float4*)&ap[0];
                w = *(const float4*)&ap[4];
            }
            __nv_bfloat162 h0 = __floats2bfloat162_rn(v.x, v.y);
            __nv_bfloat162 h1 = __floats2bfloat162_rn(v.z, v.w);
            __nv_bfloat162 h2 = __floats2bfloat162_rn(w.x, w.y);
            __nv_bfloat162 h3 = __floats2bfloat162_rn(w.z, w.w);
            __nv_bfloat162 l0 = __floats2bfloat162_rn(v.x - __low2float(h0), v.y - __high2float(h0));
            __nv_bfloat162 l1 = __floats2bfloat162_rn(v.z - __low2float(h1), v.w - __high2float(h1));
            __nv_bfloat162 l2 = __floats2bfloat162_rn(w.x - __low2float(h2), w.y - __high2float(h2));
            __nv_bfloat162 l3 = __floats2bfloat162_rn(w.z - __low2float(h3), w.w - __high2float(h3));
            int o = arl * PADK + aseg;
            *(uint4*)&Ah[o] = make_uint4(*(uint32_t*)&h0, *(uint32_t*)&h1,
                                         *(uint32_t*)&h2, *(uint32_t*)&h3);
            *(uint4*)&Al[o] = make_uint4(*(uint32_t*)&l0, *(uint32_t*)&l1,
                                         *(uint32_t*)&l2, *(uint32_t*)&l3);
        }
        // ---- stage B: 32 bf16 per thread, hi & lo ----
        {
            const uint4* bh = (const uint4*)(Bhig + (size_t)brl * K + k0 + bseg);
            const uint4* bl = (const uint4*)(Blog + (size_t)brl * K + k0 + bseg);
            int o = brl * PADK + bseg;
            #pragma unroll
            for (int s = 0; s < 4; s++) {
                *(uint4*)&Bh[o + s * 8] = bh[s];
                *(uint4*)&Bl[o + s * 8] = bl[s];
            }
        }
        __syncthreads();

        // ---- MMA: 4 k-steps of 16, ldmatrix fragments ----
        #pragma unroll
        for (int ks = 0; ks < 4; ks++) {
            int kk = ks * 16;
            uint32_t ahf[2][4], alf[2][4];
            #pragma unroll
            for (int mi = 0; mi < 2; mi++) {
                uint32_t off = (uint32_t)(((a_row + mi * 16) * PADK + kk + a_kof) * 2);
                ldsm4(ahf[mi], ah_b + off);
                ldsm4(alf[mi], al_b + off);
            }
            uint32_t bhf[4][2], blf[4][2];
            #pragma unroll
            for (int nj = 0; nj < 2; nj++) {
                uint32_t off = (uint32_t)(((b_row + nj * 16) * PADK + kk + b_kof) * 2);
                uint32_t rh[4], rl[4];
                ldsm4(rh, bh_b + off);
                ldsm4(rl, bl_b + off);
                bhf[2 * nj][0] = rh[0]; bhf[2 * nj][1] = rh[1];
                bhf[2 * nj + 1][0] = rh[2]; bhf[2 * nj + 1][1] = rh[3];
                blf[2 * nj][0] = rl[0]; blf[2 * nj][1] = rl[1];
                blf[2 * nj + 1][0] = rl[2]; blf[2 * nj + 1][1] = rl[3];
            }
            #pragma unroll
            for (int ni = 0; ni < 4; ni++)
                #pragma unroll
                for (int mi = 0; mi < 2; mi++) {
                    mma16816(acc[mi][ni], ahf[mi], bhf[ni][0], bhf[ni][1]);
                    mma16816(acc[mi][ni], ahf[mi], blf[ni][0], blf[ni][1]);
                    mma16816(acc[mi][ni], alf[mi], bhf[ni][0], bhf[ni][1]);
                }
        }
        __syncthreads();
    }

    // ---- epilogue: bias, sum-of-squares, normalize, lrelu, store ----
    #pragma unroll
    for (int mi = 0; mi < 2; mi++) {
        #pragma unroll
        for (int rh = 0; rh < 2; rh++) {
            float ss = 0.f;
            #pragma unroll
            for (int ni = 0; ni < 4; ni++) {
                int col = nbw + ni * 8 + 2 * tig;
                float c0 = acc[mi][ni][rh * 2 + 0] + bs[col];
                float c1 = acc[mi][ni][rh * 2 + 1] + bs[col + 1];
                acc[mi][ni][rh * 2 + 0] = c0;
                acc[mi][ni][rh * 2 + 1] = c1;
                ss += c0 * c0 + c1 * c1;
            }
            ss += __shfl_xor_sync(0xffffffffu, ss, 1);
            ss += __shfl_xor_sync(0xffffffffu, ss, 2);
            if (tig == 0) {
                int row = mw + mi * 16 + rh * 8 + gid;
                ssb[row * 8 + nw] = ss;
            }
        }
    }
    __syncthreads();
    if (tid < 64) {
        const float* p = &ssb[tid * 8];
        float s = p[0] + p[1] + p[2] + p[3] + p[4] + p[5] + p[6] + p[7];
        ivb[tid] = 1.f / fmaxf(sqrtf(s), EPSN);
    }
    __syncthreads();

    #pragma unroll
    for (int mi = 0; mi < 2; mi++) {
        #pragma unroll
        for (int rh = 0; rh < 2; rh++) {
            int rl = mw + mi * 16 + rh * 8 + gid;
            int grow = m0 + rl;
            if (grow >= M) continue;
            int dst = (LAYER == 2) ? g_mlist[grow] : grow;
            float inv = ivb[rl];
            float* crow = C + (size_t)dst * DH;
            #pragma unroll
            for (int ni = 0; ni < 4; ni++) {
                int col = nbw + ni * 8 + 2 * tig;
                float2 v;
                v.x = lrelu(acc[mi][ni][rh * 2 + 0] * inv);
                v.y = lrelu(acc[mi][ni][rh * 2 + 1] * inv);
                *(float2*)&crow[col] = v;
            }
        }
    }
}

// ---------------- layer 3 fused: agg + matvec + normalize ---------------------
__global__ void k_final(const float* __restrict__ W3, const float* __restrict__ b3,
                        float* __restrict__ out) {
    __shared__ float agg[DH];
    __shared__ float red[64];
    int g = blockIdx.x, tid = threadIdx.x;
    int d = g * 100;
    int beg = seg_beg(d), end = beg + g_deg[d];
    float4 acc = make_float4(0.f, 0.f, 0.f, 0.f);
    for (int j = beg; j < end; j++) {
        int s = g_csr[j];
        float4 v = *(const float4*)&g_h2[(size_t)s * DH + tid * 4];
        acc.x += v.x; acc.y += v.y; acc.z += v.z; acc.w += v.w;
    }
    *(float4*)&agg[tid * 4] = acc;
    __syncthreads();
    float o = b3[tid];
    #pragma unroll 8
    for (int k = 0; k < DH; k++) o += agg[k] * W3[k * DOUT + tid];
    red[tid] = o * o;
    __syncthreads();
    #pragma unroll
    for (int s = 32; s > 0; s >>= 1) {
        if (tid < s) red[tid] += red[tid + s];
        __syncthreads();
    }
    float inv = 1.f / fmaxf(sqrtf(red[0]), EPSN);
    out[g * DOUT + tid] = o * inv;
}

// ---------------- launcher ----------------------------------------------------
extern "C" void kernel_launch(void* const* d_in, const int* in_sizes, int n_in,
                              void* d_out, int out_size) {
    const float* x  = (const float*)d_in[0];
    const int*   ei = (const int*)d_in[1];
    const float* W1 = (const float*)d_in[3];
    const float* b1 = (const float*)d_in[4];
    const float* W2 = (const float*)d_in[5];
    const float* b2 = (const float*)d_in[6];
    const float* W3 = (const float*)d_in[7];
    const float* b3 = (const float*)d_in[8];
    float* out = (float*)d_out;

    cudaFuncSetAttribute(k_gemm_mma<1>, cudaFuncAttributeMaxDynamicSharedMemorySize, SM_TOT);
    cudaFuncSetAttribute(k_gemm_mma<2>, cudaFuncAttributeMaxDynamicSharedMemorySize, SM_TOT);

    void *p_deg, *p_mark, *p_mc, *p_done;
    cudaGetSymbolAddress(&p_deg, g_deg);
    cudaGetSymbolAddress(&p_mark, g_mark);
    cudaGetSymbolAddress(&p_mc, g_mcount);
    cudaGetSymbolAddress(&p_done, g_done);
    cudaMemsetAsync(p_deg, 0, NN * sizeof(int));
    cudaMemsetAsync(p_mark, 0, NN * sizeof(int));
    cudaMemsetAsync(p_mc, 0, sizeof(int));
    cudaMemsetAsync(p_done, 0, sizeof(int));

    const int TB = 256;
    const int nb_prep  = ((NN * DIN / 8) + TB - 1) / TB;   // 3125
    const int nb_edge4 = (NE / 4 + TB - 1) / TB;           // 782
    const int nb_warps = (NN * 32 + TB - 1) / TB;          // 6250
    const int nb_gemm  = (NN + 63) / 64;                   // 782

    k_count_prep<<<nb_prep, TB>>>(ei, x, W1, W2);   // 1
    k_scan<<<NB, TB>>>();                            // 2
    k_fill<<<nb_edge4, TB>>>(ei);                    // 3
    k_agg1<<<nb_warps, TB>>>();                      // 4  <- ncu captures agg1 now
    k_gemm_mma<1><<<nb_gemm, 512, SM_TOT>>>(b1);     // 5
    k_agg2<<<nb_warps, TB>>>();                      // 6
    k_gemm_mma<2><<<nb_gemm, 512, SM_TOT>>>(b2);     // 7
    k_final<<<NG, DOUT>>>(W3, b3, out);              // 8
}

// round 13
// speedup vs baseline: 1.0039x; 1.0039x over previous
#include <cuda_runtime.h>
#include <cuda_bf16.h>
#include <cuda_fp16.h>
#include <math.h>
#include <stdint.h>

#define NN   50000
#define NE   800000
#define DIN  128
#define DH   256
#define DOUT 64
#define NG   500
#define NEG  0.01f
#define EPSN 1e-12f
#define NB   ((NN + 255) / 256)   // 196 scan blocks

// ---------------- scratch ----------------------------------------------------
__device__ int    g_deg[NN];
__device__ int    g_rowptr[NN + 1];
__device__ int    g_rank[NE];
__device__ int    g_csr[NE];
__device__ int    g_mark[NN];
__device__ int    g_mlist[NN];
__device__ int    g_mcount;
__device__ int    g_bsum[NB];
__device__ __half g_xh[(size_t)NN * DIN];        // fp16 copy of x for gather
__device__ float  g_agg1[(size_t)NN * DIN];
__device__ float  g_h1[(size_t)NN * DH];
__device__ float  g_agg2[(size_t)NN * DH];       // compacted rows [mcount]
__device__ float  g_h2[(size_t)NN * DH];
// split weights, transposed [n][k] (col-major B for mma .row.col)
__device__ __nv_bfloat16 g_B1hi[DH * DIN];
__device__ __nv_bfloat16 g_B1lo[DH * DIN];
__device__ __nv_bfloat16 g_B2hi[DH * DH];
__device__ __nv_bfloat16 g_B2lo[DH * DH];

__device__ __forceinline__ float lrelu(float t) { return t >= 0.f ? t : NEG * t; }

__device__ __forceinline__ uint32_t smem_u32(const void* p) {
    uint32_t a;
    asm("{ .reg .u64 t; cvta.to.shared.u64 t, %1; cvt.u32.u64 %0, t; }" : "=r"(a) : "l"(p));
    return a;
}
__device__ __forceinline__ void mma16816(float* d, const uint32_t* a,
                                         uint32_t b0, uint32_t b1) {
    asm volatile(
        "mma.sync.aligned.m16n8k16.row.col.f32.bf16.bf16.f32 "
        "{%0,%1,%2,%3}, {%4,%5,%6,%7}, {%8,%9}, {%0,%1,%2,%3};"
        : "+f"(d[0]), "+f"(d[1]), "+f"(d[2]), "+f"(d[3])
        : "r"(a[0]), "r"(a[1]), "r"(a[2]), "r"(a[3]), "r"(b0), "r"(b1));
}
__device__ __forceinline__ void ldsm4(uint32_t* r, uint32_t addr) {
    asm volatile("ldmatrix.sync.aligned.m8n8.x4.shared.b16 {%0,%1,%2,%3}, [%4];"
                 : "=r"(r[0]), "=r"(r[1]), "=r"(r[2]), "=r"(r[3]) : "r"(addr));
}

// ---------------- parallel branch: fp16 conversion + weight split -------------
__global__ void k_conv(const float* __restrict__ x,
                       const float* __restrict__ W1,
                       const float* __restrict__ W2) {
    int t = blockIdx.x * blockDim.x + threadIdx.x;
    {   // fp16 conversion: 8 elements per thread, covers all 6.4M exactly
        size_t c0 = (size_t)t * 8;
        if (c0 < (size_t)NN * DIN) {
            float4 a = __ldg((const float4*)&x[c0]);
            float4 b = __ldg((const float4*)&x[c0 + 4]);
            __half2 h0 = __floats2half2_rn(a.x, a.y);
            __half2 h1 = __floats2half2_rn(a.z, a.w);
            __half2 h2 = __floats2half2_rn(b.x, b.y);
            __half2 h3 = __floats2half2_rn(b.z, b.w);
            *(uint4*)&g_xh[c0] = make_uint4(*(uint32_t*)&h0, *(uint32_t*)&h1,
                                            *(uint32_t*)&h2, *(uint32_t*)&h3);
        }
    }
    if (t < DIN * DH) {           // W1: [k][n]
        int k = t / DH, n = t % DH;
        float f = W1[t];
        __nv_bfloat16 h = __float2bfloat16(f);
        g_B1hi[n * DIN + k] = h;
        g_B1lo[n * DIN + k] = __float2bfloat16(f - __bfloat162float(h));
    }
    if (t < DH * DH) {            // W2: [k][n]
        int k = t / DH, n = t % DH;
        float f = W2[t];
        __nv_bfloat16 h = __float2bfloat16(f);
        g_B2hi[n * DH + k] = h;
        g_B2lo[n * DH + k] = __float2bfloat16(f - __bfloat162float(h));
    }
}

// ---------------- graph chain: count -> scan -> fill ---------------------------
__global__ void k_count(const int* __restrict__ ei) {
    int t = blockIdx.x * blockDim.x + threadIdx.x;
    int e0 = t * 4;
    if (e0 >= NE) return;
    int4 s4 = *(const int4*)&ei[e0];
    int4 d4 = *(const int4*)&ei[NE + e0];
    int r0 = atomicAdd(&g_deg[d4.x], 1);
    int r1 = atomicAdd(&g_deg[d4.y], 1);
    int r2 = atomicAdd(&g_deg[d4.z], 1);
    int r3 = atomicAdd(&g_deg[d4.w], 1);
    *(int4*)&g_rank[e0] = make_int4(r0, r1, r2, r3);
    if (d4.x % 100 == 0) g_mark[s4.x] = 1;
    if (d4.y % 100 == 0) g_mark[s4.y] = 1;
    if (d4.z % 100 == 0) g_mark[s4.z] = 1;
    if (d4.w % 100 == 0) g_mark[s4.w] = 1;
}

__device__ __forceinline__ int block_scan_inc(int v, int tid, int* ws) {
    int lane = tid & 31, wd = tid >> 5;
    int x = v;
    #pragma unroll
    for (int o = 1; o < 32; o <<= 1) {
        int t = __shfl_up_sync(0xffffffffu, x, o);
        if (lane >= o) x += t;
    }
    if (lane == 31) ws[wd] = x;
    __syncthreads();
    if (tid < 8) {
        int s = ws[tid];
        #pragma unroll
        for (int o = 1; o < 8; o <<= 1) {
            int t = __shfl_up_sync(0xffu, s, o);
            if (tid >= o) s += t;
        }
        ws[tid] = s;
    }
    __syncthreads();
    return x + (wd ? ws[wd - 1] : 0);
}

__global__ void k_scan1() {
    __shared__ int ws[8];
    int tid = threadIdx.x;
    int gi = blockIdx.x * 256 + tid;
    int v = (gi < NN) ? g_deg[gi] : 0;
    int inc = block_scan_inc(v, tid, ws);
    if (gi < NN) g_rowptr[gi + 1] = inc;
    if (tid == 255) g_bsum[blockIdx.x] = inc;
}

__global__ void k_scan23c() {
    __shared__ int ws[8];
    __shared__ int s_off;
    int tid = threadIdx.x, bid = blockIdx.x;
    int v2 = (tid < NB) ? g_bsum[tid] : 0;
    int inc2 = block_scan_inc(v2, tid, ws);
    if (tid == bid) s_off = inc2 - v2;   // exclusive prefix for this block
    __syncthreads();
    int gi = bid * 256 + tid;
    if (gi >= NN) return;
    int inc = g_rowptr[gi + 1] + s_off;
    g_rowptr[gi + 1] = inc;
    if (gi == 0) g_rowptr[0] = 0;
    if (g_mark[gi]) {
        int p = atomicAdd(&g_mcount, 1);
        g_mlist[p] = gi;
    }
}

// atomic-free scatter: position = rowptr[dst] + precomputed rank
__global__ void k_fill(const int* __restrict__ ei) {
    int t = blockIdx.x * blockDim.x + threadIdx.x;
    int e0 = t * 4;
    if (e0 >= NE) return;
    int4 s4 = *(const int4*)&ei[e0];
    int4 d4 = *(const int4*)&ei[NE + e0];
    int4 r4 = *(const int4*)&g_rank[e0];
    g_csr[g_rowptr[d4.x] + r4.x] = s4.x;
    g_csr[g_rowptr[d4.y] + r4.y] = s4.y;
    g_csr[g_rowptr[d4.z] + r4.z] = s4.z;
    g_csr[g_rowptr[d4.w] + r4.w] = s4.w;
}

// ---------------- aggregation (warp per node, fp16 gather, fp32 accumulate) ---
__global__ void k_agg1() {
    int w    = (blockIdx.x * blockDim.x + threadIdx.x) >> 5;
    int lane = threadIdx.x & 31;
    if (w >= NN) return;
    int beg = g_rowptr[w], end = g_rowptr[w + 1];
    float4 acc = make_float4(0.f, 0.f, 0.f, 0.f);
    int j = beg;
    for (; j + 4 <= end; j += 4) {
        int s0 = g_csr[j], s1 = g_csr[j + 1], s2 = g_csr[j + 2], s3 = g_csr[j + 3];
        uint2 u0 = __ldg((const uint2*)&g_xh[(size_t)s0 * DIN + lane * 4]);
        uint2 u1 = __ldg((const uint2*)&g_xh[(size_t)s1 * DIN + lane * 4]);
        uint2 u2 = __ldg((const uint2*)&g_xh[(size_t)s2 * DIN + lane * 4]);
        uint2 u3 = __ldg((const uint2*)&g_xh[(size_t)s3 * DIN + lane * 4]);
        float2 a0 = __half22float2(*(__half2*)&u0.x), b0 = __half22float2(*(__half2*)&u0.y);
        float2 a1 = __half22float2(*(__half2*)&u1.x), b1 = __half22float2(*(__half2*)&u1.y);
        float2 a2 = __half22float2(*(__half2*)&u2.x), b2 = __half22float2(*(__half2*)&u2.y);
        float2 a3 = __half22float2(*(__half2*)&u3.x), b3 = __half22float2(*(__half2*)&u3.y);
        acc.x += a0.x + a1.x + a2.x + a3.x;
        acc.y += a0.y + a1.y + a2.y + a3.y;
        acc.z += b0.x + b1.x + b2.x + b3.x;
        acc.w += b0.y + b1.y + b2.y + b3.y;
    }
    for (; j < end; j++) {
        int s = g_csr[j];
        uint2 u = __ldg((const uint2*)&g_xh[(size_t)s * DIN + lane * 4]);
        float2 a = __half22float2(*(__half2*)&u.x), b = __half22float2(*(__half2*)&u.y);
        acc.x += a.x; acc.y += a.y; acc.z += b.x; acc.w += b.y;
    }
    *(float4*)&g_agg1[(size_t)w * DIN + lane * 4] = acc;
}

// agg2 writes COMPACTED rows (row w = position in mlist)
__global__ void k_agg2() {
    int w    = (blockIdx.x * blockDim.x + threadIdx.x) >> 5;
    int lane = threadIdx.x & 31;
    if (w >= g_mcount) return;
    int v   = g_mlist[w];
    int beg = g_rowptr[v], end = g_rowptr[v + 1];
    float4 a0 = make_float4(0.f, 0.f, 0.f, 0.f);
    float4 a1 = make_float4(0.f, 0.f, 0.f, 0.f);
    for (int j = beg; j < end; j++) {
        int s = g_csr[j];
        const float* r = &g_h1[(size_t)s * DH];
        float4 v0 = *(const float4*)&r[lane * 4];
        float4 v1 = *(const float4*)&r[128 + lane * 4];
        a0.x += v0.x; a0.y += v0.y; a0.z += v0.z; a0.w += v0.w;
        a1.x += v1.x; a1.y += v1.y; a1.z += v1.z; a1.w += v1.w;
    }
    float* o = &g_agg2[(size_t)w * DH];
    *(float4*)&o[lane * 4]       = a0;
    *(float4*)&o[128 + lane * 4] = a1;
}

// ---------------- mma.sync split-bf16 GEMM + fused bias/L2norm/leakyrelu ------
// 512 threads = 16 warps (2m x 8n), tile 64m x 256n, K chunks of 64 (R8 config).
#define PADK 72
#define SM_AHI  0
#define SM_ALO  (SM_AHI + 64 * PADK * 2)
#define SM_BHI  (SM_ALO + 64 * PADK * 2)
#define SM_BLO  (SM_BHI + 256 * PADK * 2)
#define SM_BIAS (SM_BLO + 256 * PADK * 2)
#define SM_SS   (SM_BIAS + DH * 4)
#define SM_INV  (SM_SS + 64 * 8 * 4)
#define SM_TOT  (SM_INV + 64 * 4)

template <int LAYER>
__global__ void __launch_bounds__(512, 1)
k_gemm_mma(const float* __restrict__ bias) {
    constexpr int K     = (LAYER == 1) ? DIN : DH;
    constexpr int KITER = K / 64;
    extern __shared__ char smem[];
    __nv_bfloat16* Ah = (__nv_bfloat16*)(smem + SM_AHI);
    __nv_bfloat16* Al = (__nv_bfloat16*)(smem + SM_ALO);
    __nv_bfloat16* Bh = (__nv_bfloat16*)(smem + SM_BHI);
    __nv_bfloat16* Bl = (__nv_bfloat16*)(smem + SM_BLO);
    float* bs  = (float*)(smem + SM_BIAS);
    float* ssb = (float*)(smem + SM_SS);
    float* ivb = (float*)(smem + SM_INV);

    int M = (LAYER == 1) ? NN : g_mcount;
    int m0 = blockIdx.x * 64;
    if (m0 >= M) return;

    int tid = threadIdx.x, wid = tid >> 5, lane = tid & 31;
    int gid = lane >> 2, tig = lane & 3;
    int mw = (wid >> 3) * 32;       // 2 m warp-rows
    int nw = wid & 7;               // 8 n warps
    int nbw = nw * 32;

    if (tid < DH) bs[tid] = bias[tid];

    const float* A = (LAYER == 1) ? g_agg1 : g_agg2;
    const __nv_bfloat16* Bhig = (LAYER == 1) ? g_B1hi : g_B2hi;
    const __nv_bfloat16* Blog = (LAYER == 1) ? g_B1lo : g_B2lo;
    float* C = (LAYER == 1) ? g_h1 : g_h2;

    // A staging map: thread -> row tid>>3 (0..63), seg (tid&7)*8
    int  arl    = tid >> 3;
    int  aseg   = (tid & 7) * 8;
    int  agrow  = m0 + arl;
    bool avalid = agrow < M;
    const float* arowp = A + (size_t)(avalid ? agrow : 0) * K;
    // B staging map: thread -> row tid>>1 (0..255), half (tid&1)*32
    int brl  = tid >> 1;
    int bseg = (tid & 1) * 32;

    // ldmatrix lane maps
    uint32_t ah_b = smem_u32(Ah), al_b = smem_u32(Al);
    uint32_t bh_b = smem_u32(Bh), bl_b = smem_u32(Bl);
    int a_row = mw + (lane & 7) + ((lane >> 3) & 1) * 8;   // + mi*16
    int a_kof = (lane >> 4) * 8;
    int b_row = nbw + (lane & 7) + ((lane >> 4) & 1) * 8;  // + nj*16
    int b_kof = ((lane >> 3) & 1) * 8;

    float acc[2][4][4];
    #pragma unroll
    for (int mi = 0; mi < 2; mi++)
        #pragma unroll
        for (int ni = 0; ni < 4; ni++)
            #pragma unroll
            for (int q = 0; q < 4; q++) acc[mi][ni][q] = 0.f;

    for (int it = 0; it < KITER; it++) {
        int k0 = it * 64;
        // ---- stage A: 8 fp32 per thread -> bf16 hi/lo ----
        {
            float4 v = make_float4(0.f, 0.f, 0.f, 0.f), w = v;
            if (avalid) {
                const float* ap = arowp + k0 + aseg;
                v = *(const float4*)&ap[0];
                w = *(const float4*)&ap[4];
            }
            __nv_bfloat162 h0 = __floats2bfloat162_rn(v.x, v.y);
            __nv_bfloat162 h1 = __floats2bfloat162_rn(v.z, v.w);
            __nv_bfloat162 h2 = __floats2bfloat162_rn(w.x, w.y);
            __nv_bfloat162 h3 = __floats2bfloat162_rn(w.z, w.w);
            __nv_bfloat162 l0 = __floats2bfloat162_rn(v.x - __low2float(h0), v.y - __high2float(h0));
            __nv_bfloat162 l1 = __floats2bfloat162_rn(v.z - __low2float(h1), v.w - __high2float(h1));
            __nv_bfloat162 l2 = __floats2bfloat162_rn(w.x - __low2float(h2), w.y - __high2float(h2));
            __nv_bfloat162 l3 = __floats2bfloat162_rn(w.z - __low2float(h3), w.w - __high2float(h3));
            int o = arl * PADK + aseg;
            *(uint4*)&Ah[o] = make_uint4(*(uint32_t*)&h0, *(uint32_t*)&h1,
                                         *(uint32_t*)&h2, *(uint32_t*)&h3);
            *(uint4*)&Al[o] = make_uint4(*(uint32_t*)&l0, *(uint32_t*)&l1,
                                         *(uint32_t*)&l2, *(uint32_t*)&l3);
        }
        // ---- stage B: 32 bf16 per thread, hi & lo ----
        {
            const uint4* bh = (const uint4*)(Bhig + (size_t)brl * K + k0 + bseg);
            const uint4* bl = (const uint4*)(Blog + (size_t)brl * K + k0 + bseg);
            int o = brl * PADK + bseg;
            #pragma unroll
            for (int s = 0; s < 4; s++) {
                *(uint4*)&Bh[o + s * 8] = bh[s];
                *(uint4*)&Bl[o + s * 8] = bl[s];
            }
        }
        __syncthreads();

        // ---- MMA: 4 k-steps of 16, ldmatrix fragments ----
        #pragma unroll
        for (int ks = 0; ks < 4; ks++) {
            int kk = ks * 16;
            uint32_t ahf[2][4], alf[2][4];
            #pragma unroll
            for (int mi = 0; mi < 2; mi++) {
                uint32_t off = (uint32_t)(((a_row + mi * 16) * PADK + kk + a_kof) * 2);
                ldsm4(ahf[mi], ah_b + off);
                ldsm4(alf[mi], al_b + off);
            }
            uint32_t bhf[4][2], blf[4][2];
            #pragma unroll
            for (int nj = 0; nj < 2; nj++) {
                uint32_t off = (uint32_t)(((b_row + nj * 16) * PADK + kk + b_kof) * 2);
                uint32_t rh[4], rl[4];
                ldsm4(rh, bh_b + off);
                ldsm4(rl, bl_b + off);
                bhf[2 * nj][0] = rh[0]; bhf[2 * nj][1] = rh[1];
                bhf[2 * nj + 1][0] = rh[2]; bhf[2 * nj + 1][1] = rh[3];
                blf[2 * nj][0] = rl[0]; blf[2 * nj][1] = rl[1];
                blf[2 * nj + 1][0] = rl[2]; blf[2 * nj + 1][1] = rl[3];
            }
            #pragma unroll
            for (int ni = 0; ni < 4; ni++)
                #pragma unroll
                for (int mi = 0; mi < 2; mi++) {
                    mma16816(acc[mi][ni], ahf[mi], bhf[ni][0], bhf[ni][1]);
                    mma16816(acc[mi][ni], ahf[mi], blf[ni][0], blf[ni][1]);
                    mma16816(acc[mi][ni], alf[mi], bhf[ni][0], bhf[ni][1]);
                }
        }
        __syncthreads();
    }

    // ---- epilogue: bias, sum-of-squares, normalize, lrelu, store ----
    #pragma unroll
    for (int mi = 0; mi < 2; mi++) {
        #pragma unroll
        for (int rh = 0; rh < 2; rh++) {
            float ss = 0.f;
            #pragma unroll
            for (int ni = 0; ni < 4; ni++) {
                int col = nbw + ni * 8 + 2 * tig;
                float c0 = acc[mi][ni][rh * 2 + 0] + bs[col];
                float c1 = acc[mi][ni][rh * 2 + 1] + bs[col + 1];
                acc[mi][ni][rh * 2 + 0] = c0;
                acc[mi][ni][rh * 2 + 1] = c1;
                ss += c0 * c0 + c1 * c1;
            }
            ss += __shfl_xor_sync(0xffffffffu, ss, 1);
            ss += __shfl_xor_sync(0xffffffffu, ss, 2);
            if (tig == 0) {
                int row = mw + mi * 16 + rh * 8 + gid;
                ssb[row * 8 + nw] = ss;
            }
        }
    }
    __syncthreads();
    if (tid < 64) {
        const float* p = &ssb[tid * 8];
        float s = p[0] + p[1] + p[2] + p[3] + p[4] + p[5] + p[6] + p[7];
        ivb[tid] = 1.f / fmaxf(sqrtf(s), EPSN);
    }
    __syncthreads();

    #pragma unroll
    for (int mi = 0; mi < 2; mi++) {
        #pragma unroll
        for (int rh = 0; rh < 2; rh++) {
            int rl = mw + mi * 16 + rh * 8 + gid;
            int grow = m0 + rl;
            if (grow >= M) continue;
            int dst = (LAYER == 2) ? g_mlist[grow] : grow;
            float inv = ivb[rl];
            float* crow = C + (size_t)dst * DH;
            #pragma unroll
            for (int ni = 0; ni < 4; ni++) {
                int col = nbw + ni * 8 + 2 * tig;
                float2 v;
                v.x = lrelu(acc[mi][ni][rh * 2 + 0] * inv);
                v.y = lrelu(acc[mi][ni][rh * 2 + 1] * inv);
                *(float2*)&crow[col] = v;
            }
        }
    }
}

// ---------------- layer 3 fused: agg + matvec + normalize ---------------------
__global__ void k_final(const float* __restrict__ W3, const float* __restrict__ b3,
                        float* __restrict__ out) {
    __shared__ float agg[DH];
    __shared__ float red[64];
    int g = blockIdx.x, tid = threadIdx.x;
    int d = g * 100;
    int beg = g_rowptr[d], end = g_rowptr[d + 1];
    float4 acc = make_float4(0.f, 0.f, 0.f, 0.f);
    for (int j = beg; j < end; j++) {
        int s = g_csr[j];
        float4 v = *(const float4*)&g_h2[(size_t)s * DH + tid * 4];
        acc.x += v.x; acc.y += v.y; acc.z += v.z; acc.w += v.w;
    }
    *(float4*)&agg[tid * 4] = acc;
    __syncthreads();
    float o = b3[tid];
    #pragma unroll 8
    for (int k = 0; k < DH; k++) o += agg[k] * W3[k * DOUT + tid];
    red[tid] = o * o;
    __syncthreads();
    #pragma unroll
    for (int s = 32; s > 0; s >>= 1) {
        if (tid < s) red[tid] += red[tid + s];
        __syncthreads();
    }
    float inv = 1.f / fmaxf(sqrtf(red[0]), EPSN);
    out[g * DOUT + tid] = o * inv;
}

// ---------------- launcher ----------------------------------------------------
extern "C" void kernel_launch(void* const* d_in, const int* in_sizes, int n_in,
                              void* d_out, int out_size) {
    const float* x  = (const float*)d_in[0];
    const int*   ei = (const int*)d_in[1];
    const float* W1 = (const float*)d_in[3];
    const float* b1 = (const float*)d_in[4];
    const float* W2 = (const float*)d_in[5];
    const float* b2 = (const float*)d_in[6];
    const float* W3 = (const float*)d_in[7];
    const float* b3 = (const float*)d_in[8];
    float* out = (float*)d_out;

    // one-time resources (created on first call = correctness run, not during capture)
    static cudaStream_t s2 = nullptr;
    static cudaEvent_t ev_fork = nullptr, ev_join = nullptr;
    if (s2 == nullptr) {
        cudaStreamCreateWithFlags(&s2, cudaStreamNonBlocking);
        cudaEventCreateWithFlags(&ev_fork, cudaEventDisableTiming);
        cudaEventCreateWithFlags(&ev_join, cudaEventDisableTiming);
    }

    cudaFuncSetAttribute(k_gemm_mma<1>, cudaFuncAttributeMaxDynamicSharedMemorySize, SM_TOT);
    cudaFuncSetAttribute(k_gemm_mma<2>, cudaFuncAttributeMaxDynamicSharedMemorySize, SM_TOT);

    void *p_deg, *p_mark, *p_mc;
    cudaGetSymbolAddress(&p_deg, g_deg);
    cudaGetSymbolAddress(&p_mark, g_mark);
    cudaGetSymbolAddress(&p_mc, g_mcount);
    cudaMemsetAsync(p_deg, 0, NN * sizeof(int));
    cudaMemsetAsync(p_mark, 0, NN * sizeof(int));
    cudaMemsetAsync(p_mc, 0, sizeof(int));

    const int TB = 256;
    const int nb_conv  = ((NN * DIN / 8) + TB - 1) / TB;   // 3125
    const int nb_edge4 = (NE / 4 + TB - 1) / TB;           // 782
    const int nb_warps = (NN * 32 + TB - 1) / TB;          // 6250
    const int nb_gemm  = (NN + 63) / 64;                   // 782

    // fork: conversion + weight split run parallel to the graph chain
    cudaEventRecord(ev_fork, 0);
    cudaStreamWaitEvent(s2, ev_fork, 0);
    k_conv<<<nb_conv, TB, 0, s2>>>(x, W1, W2);
    cudaEventRecord(ev_join, s2);

    // main chain
    k_count<<<nb_edge4, TB>>>(ei);
    k_scan1<<<NB, TB>>>();
    k_scan23c<<<NB, TB>>>();
    k_fill<<<nb_edge4, TB>>>(ei);

    // join before consumers of g_xh / g_B*
    cudaStreamWaitEvent(0, ev_join, 0);

    k_agg1<<<nb_warps, TB>>>();
    k_gemm_mma<1><<<nb_gemm, 512, SM_TOT>>>(b1);
    k_agg2<<<nb_warps, TB>>>();
    k_gemm_mma<2><<<nb_gemm, 512, SM_TOT>>>(b2);
    k_final<<<NG, DOUT>>>(W3, b3, out);
}

// round 14
// speedup vs baseline: 1.0658x; 1.0616x over previous
#include <cuda_runtime.h>
#include <cuda_bf16.h>
#include <cuda_fp16.h>
#include <math.h>
#include <stdint.h>

#define NN   50000
#define NE   800000
#define DIN  128
#define DH   256
#define DOUT 64
#define NG   500
#define NEG  0.01f
#define EPSN 1e-12f
#define NB   ((NN + 255) / 256)   // 196 scan blocks

// ---------------- scratch ----------------------------------------------------
__device__ int    g_deg[NN];
__device__ int    g_rowptr[NN + 1];
__device__ int    g_rank[NE];
__device__ int    g_csr[NE];
__device__ int    g_mark[NN];
__device__ int    g_mlist[NN];
__device__ int    g_mcount;
__device__ int    g_bsum[NB];
__device__ __half g_xh[(size_t)NN * DIN];        // fp16 copy of x for gather
__device__ float  g_agg1[(size_t)NN * DIN];
__device__ float  g_h1[(size_t)NN * DH];
__device__ float  g_agg2[(size_t)NN * DH];       // compacted rows [mcount]
__device__ float  g_h2[(size_t)NN * DH];
// split weights, transposed [n][k] (col-major B for mma .row.col)
__device__ __nv_bfloat16 g_B1hi[DH * DIN];
__device__ __nv_bfloat16 g_B1lo[DH * DIN];
__device__ __nv_bfloat16 g_B2hi[DH * DH];
__device__ __nv_bfloat16 g_B2lo[DH * DH];

__device__ __forceinline__ float lrelu(float t) { return t >= 0.f ? t : NEG * t; }

__device__ __forceinline__ uint32_t smem_u32(const void* p) {
    uint32_t a;
    asm("{ .reg .u64 t; cvta.to.shared.u64 t, %1; cvt.u32.u64 %0, t; }" : "=r"(a) : "l"(p));
    return a;
}
__device__ __forceinline__ void mma16816(float* d, const uint32_t* a,
                                         uint32_t b0, uint32_t b1) {
    asm volatile(
        "mma.sync.aligned.m16n8k16.row.col.f32.bf16.bf16.f32 "
        "{%0,%1,%2,%3}, {%4,%5,%6,%7}, {%8,%9}, {%0,%1,%2,%3};"
        : "+f"(d[0]), "+f"(d[1]), "+f"(d[2]), "+f"(d[3])
        : "r"(a[0]), "r"(a[1]), "r"(a[2]), "r"(a[3]), "r"(b0), "r"(b1));
}
__device__ __forceinline__ void ldsm4(uint32_t* r, uint32_t addr) {
    asm volatile("ldmatrix.sync.aligned.m8n8.x4.shared.b16 {%0,%1,%2,%3}, [%4];"
                 : "=r"(r[0]), "=r"(r[1]), "=r"(r[2]), "=r"(r[3]) : "r"(addr));
}

// ---------------- preprocessing ----------------------------------------------
// count (stores per-edge rank) + mark + weight split + fp16 x conversion
__global__ void k_count_prep(const int* __restrict__ ei,
                             const float* __restrict__ x,
                             const float* __restrict__ W1,
                             const float* __restrict__ W2) {
    int t = blockIdx.x * blockDim.x + threadIdx.x;
    {   // fp16 conversion: 8 elements per thread, covers all 6.4M exactly
        size_t c0 = (size_t)t * 8;
        if (c0 < (size_t)NN * DIN) {
            float4 a = __ldg((const float4*)&x[c0]);
            float4 b = __ldg((const float4*)&x[c0 + 4]);
            __half2 h0 = __floats2half2_rn(a.x, a.y);
            __half2 h1 = __floats2half2_rn(a.z, a.w);
            __half2 h2 = __floats2half2_rn(b.x, b.y);
            __half2 h3 = __floats2half2_rn(b.z, b.w);
            *(uint4*)&g_xh[c0] = make_uint4(*(uint32_t*)&h0, *(uint32_t*)&h1,
                                            *(uint32_t*)&h2, *(uint32_t*)&h3);
        }
    }
    int e0 = t * 4;
    if (e0 < NE) {
        int4 s4 = *(const int4*)&ei[e0];
        int4 d4 = *(const int4*)&ei[NE + e0];
        int r0 = atomicAdd(&g_deg[d4.x], 1);
        int r1 = atomicAdd(&g_deg[d4.y], 1);
        int r2 = atomicAdd(&g_deg[d4.z], 1);
        int r3 = atomicAdd(&g_deg[d4.w], 1);
        *(int4*)&g_rank[e0] = make_int4(r0, r1, r2, r3);
        if (d4.x % 100 == 0) g_mark[s4.x] = 1;
        if (d4.y % 100 == 0) g_mark[s4.y] = 1;
        if (d4.z % 100 == 0) g_mark[s4.z] = 1;
        if (d4.w % 100 == 0) g_mark[s4.w] = 1;
    }
    if (t < DIN * DH) {           // W1: [k][n]
        int k = t / DH, n = t % DH;
        float f = W1[t];
        __nv_bfloat16 h = __float2bfloat16(f);
        g_B1hi[n * DIN + k] = h;
        g_B1lo[n * DIN + k] = __float2bfloat16(f - __bfloat162float(h));
    }
    if (t < DH * DH) {            // W2: [k][n]
        int k = t / DH, n = t % DH;
        float f = W2[t];
        __nv_bfloat16 h = __float2bfloat16(f);
        g_B2hi[n * DH + k] = h;
        g_B2lo[n * DH + k] = __float2bfloat16(f - __bfloat162float(h));
    }
}

__device__ __forceinline__ int block_scan_inc(int v, int tid, int* ws) {
    int lane = tid & 31, wd = tid >> 5;
    int x = v;
    #pragma unroll
    for (int o = 1; o < 32; o <<= 1) {
        int t = __shfl_up_sync(0xffffffffu, x, o);
        if (lane >= o) x += t;
    }
    if (lane == 31) ws[wd] = x;
    __syncthreads();
    if (tid < 8) {
        int s = ws[tid];
        #pragma unroll
        for (int o = 1; o < 8; o <<= 1) {
            int t = __shfl_up_sync(0xffu, s, o);
            if (tid >= o) s += t;
        }
        ws[tid] = s;
    }
    __syncthreads();
    return x + (wd ? ws[wd - 1] : 0);
}

__global__ void k_scan1() {
    __shared__ int ws[8];
    int tid = threadIdx.x;
    int gi = blockIdx.x * 256 + tid;
    int v = (gi < NN) ? g_deg[gi] : 0;
    int inc = block_scan_inc(v, tid, ws);
    if (gi < NN) g_rowptr[gi + 1] = inc;
    if (tid == 255) g_bsum[blockIdx.x] = inc;
}

__global__ void k_scan23c() {
    __shared__ int ws[8];
    __shared__ int s_off;
    int tid = threadIdx.x, bid = blockIdx.x;
    int v2 = (tid < NB) ? g_bsum[tid] : 0;
    int inc2 = block_scan_inc(v2, tid, ws);
    if (tid == bid) s_off = inc2 - v2;   // exclusive prefix for this block
    __syncthreads();
    int gi = bid * 256 + tid;
    if (gi >= NN) return;
    int inc = g_rowptr[gi + 1] + s_off;
    g_rowptr[gi + 1] = inc;
    if (gi == 0) g_rowptr[0] = 0;
    if (g_mark[gi]) {
        int p = atomicAdd(&g_mcount, 1);
        g_mlist[p] = gi;
    }
}

// atomic-free scatter: position = rowptr[dst] + precomputed rank
__global__ void k_fill(const int* __restrict__ ei) {
    int t = blockIdx.x * blockDim.x + threadIdx.x;
    int e0 = t * 4;
    if (e0 >= NE) return;
    int4 s4 = *(const int4*)&ei[e0];
    int4 d4 = *(const int4*)&ei[NE + e0];
    int4 r4 = *(const int4*)&g_rank[e0];
    g_csr[g_rowptr[d4.x] + r4.x] = s4.x;
    g_csr[g_rowptr[d4.y] + r4.y] = s4.y;
    g_csr[g_rowptr[d4.z] + r4.z] = s4.z;
    g_csr[g_rowptr[d4.w] + r4.w] = s4.w;
}

// ---------------- aggregation (warp per node, fp16 gather, fp32 accumulate) ---
__global__ void k_agg1() {
    int w    = (blockIdx.x * blockDim.x + threadIdx.x) >> 5;
    int lane = threadIdx.x & 31;
    if (w >= NN) return;
    int beg = g_rowptr[w], end = g_rowptr[w + 1];
    float4 acc = make_float4(0.f, 0.f, 0.f, 0.f);
    int j = beg;
    for (; j + 4 <= end; j += 4) {
        int s0 = g_csr[j], s1 = g_csr[j + 1], s2 = g_csr[j + 2], s3 = g_csr[j + 3];
        uint2 u0 = __ldg((const uint2*)&g_xh[(size_t)s0 * DIN + lane * 4]);
        uint2 u1 = __ldg((const uint2*)&g_xh[(size_t)s1 * DIN + lane * 4]);
        uint2 u2 = __ldg((const uint2*)&g_xh[(size_t)s2 * DIN + lane * 4]);
        uint2 u3 = __ldg((const uint2*)&g_xh[(size_t)s3 * DIN + lane * 4]);
        float2 a0 = __half22float2(*(__half2*)&u0.x), b0 = __half22float2(*(__half2*)&u0.y);
        float2 a1 = __half22float2(*(__half2*)&u1.x), b1 = __half22float2(*(__half2*)&u1.y);
        float2 a2 = __half22float2(*(__half2*)&u2.x), b2 = __half22float2(*(__half2*)&u2.y);
        float2 a3 = __half22float2(*(__half2*)&u3.x), b3 = __half22float2(*(__half2*)&u3.y);
        acc.x += a0.x + a1.x + a2.x + a3.x;
        acc.y += a0.y + a1.y + a2.y + a3.y;
        acc.z += b0.x + b1.x + b2.x + b3.x;
        acc.w += b0.y + b1.y + b2.y + b3.y;
    }
    for (; j < end; j++) {
        int s = g_csr[j];
        uint2 u = __ldg((const uint2*)&g_xh[(size_t)s * DIN + lane * 4]);
        float2 a = __half22float2(*(__half2*)&u.x), b = __half22float2(*(__half2*)&u.y);
        acc.x += a.x; acc.y += a.y; acc.z += b.x; acc.w += b.y;
    }
    *(float4*)&g_agg1[(size_t)w * DIN + lane * 4] = acc;
}

// agg2 writes COMPACTED rows (row w = position in mlist)
__global__ void k_agg2() {
    int w    = (blockIdx.x * blockDim.x + threadIdx.x) >> 5;
    int lane = threadIdx.x & 31;
    if (w >= g_mcount) return;
    int v   = g_mlist[w];
    int beg = g_rowptr[v], end = g_rowptr[v + 1];
    float4 a0 = make_float4(0.f, 0.f, 0.f, 0.f);
    float4 a1 = make_float4(0.f, 0.f, 0.f, 0.f);
    for (int j = beg; j < end; j++) {
        int s = g_csr[j];
        const float* r = &g_h1[(size_t)s * DH];
        float4 v0 = *(const float4*)&r[lane * 4];
        float4 v1 = *(const float4*)&r[128 + lane * 4];
        a0.x += v0.x; a0.y += v0.y; a0.z += v0.z; a0.w += v0.w;
        a1.x += v1.x; a1.y += v1.y; a1.z += v1.z; a1.w += v1.w;
    }
    float* o = &g_agg2[(size_t)w * DH];
    *(float4*)&o[lane * 4]       = a0;
    *(float4*)&o[128 + lane * 4] = a1;
}

// ---------------- mma.sync split-bf16 GEMM + fused bias/L2norm/leakyrelu ------
// 512 threads = 16 warps (2m x 8n), tile 64m x 256n, K chunks of 64,
// register-prefetch software pipeline on A/B staging.
#define PADK 72
#define SM_AHI  0
#define SM_ALO  (SM_AHI + 64 * PADK * 2)
#define SM_BHI  (SM_ALO + 64 * PADK * 2)
#define SM_BLO  (SM_BHI + 256 * PADK * 2)
#define SM_BIAS (SM_BLO + 256 * PADK * 2)
#define SM_SS   (SM_BIAS + DH * 4)
#define SM_INV  (SM_SS + 64 * 8 * 4)
#define SM_TOT  (SM_INV + 64 * 4)

template <int LAYER>
__global__ void __launch_bounds__(512, 1)
k_gemm_mma(const float* __restrict__ bias) {
    constexpr int K     = (LAYER == 1) ? DIN : DH;
    constexpr int KITER = K / 64;
    extern __shared__ char smem[];
    __nv_bfloat16* Ah = (__nv_bfloat16*)(smem + SM_AHI);
    __nv_bfloat16* Al = (__nv_bfloat16*)(smem + SM_ALO);
    __nv_bfloat16* Bh = (__nv_bfloat16*)(smem + SM_BHI);
    __nv_bfloat16* Bl = (__nv_bfloat16*)(smem + SM_BLO);
    float* bs  = (float*)(smem + SM_BIAS);
    float* ssb = (float*)(smem + SM_SS);
    float* ivb = (float*)(smem + SM_INV);

    int M = (LAYER == 1) ? NN : g_mcount;
    int m0 = blockIdx.x * 64;
    if (m0 >= M) return;

    int tid = threadIdx.x, wid = tid >> 5, lane = tid & 31;
    int gid = lane >> 2, tig = lane & 3;
    int mw = (wid >> 3) * 32;       // 2 m warp-rows
    int nw = wid & 7;               // 8 n warps
    int nbw = nw * 32;

    if (tid < DH) bs[tid] = bias[tid];

    const float* A = (LAYER == 1) ? g_agg1 : g_agg2;
    const __nv_bfloat16* Bhig = (LAYER == 1) ? g_B1hi : g_B2hi;
    const __nv_bfloat16* Blog = (LAYER == 1) ? g_B1lo : g_B2lo;
    float* C = (LAYER == 1) ? g_h1 : g_h2;

    // A staging map: thread -> row tid>>3 (0..63), seg (tid&7)*8
    int  arl    = tid >> 3;
    int  aseg   = (tid & 7) * 8;
    int  agrow  = m0 + arl;
    bool avalid = agrow < M;
    const float* arowp = A + (size_t)(avalid ? agrow : 0) * K;
    // B staging map: thread -> row tid>>1 (0..255), half (tid&1)*32
    int brl  = tid >> 1;
    int bseg = (tid & 1) * 32;
    const uint4* bhp = (const uint4*)(Bhig + (size_t)brl * K + bseg);
    const uint4* blp = (const uint4*)(Blog + (size_t)brl * K + bseg);

    // ldmatrix lane maps
    uint32_t ah_b = smem_u32(Ah), al_b = smem_u32(Al);
    uint32_t bh_b = smem_u32(Bh), bl_b = smem_u32(Bl);
    int a_row = mw + (lane & 7) + ((lane >> 3) & 1) * 8;   // + mi*16
    int a_kof = (lane >> 4) * 8;
    int b_row = nbw + (lane & 7) + ((lane >> 4) & 1) * 8;  // + nj*16
    int b_kof = ((lane >> 3) & 1) * 8;

    float acc[2][4][4];
    #pragma unroll
    for (int mi = 0; mi < 2; mi++)
        #pragma unroll
        for (int ni = 0; ni < 4; ni++)
            #pragma unroll
            for (int q = 0; q < 4; q++) acc[mi][ni][q] = 0.f;

    // prefetch registers
    float4 av, aw;
    uint4  bhv[4], blv[4];

    // ---- prologue: load chunk 0 ----
    {
        if (avalid) {
            av = *(const float4*)&arowp[aseg];
            aw = *(const float4*)&arowp[aseg + 4];
        } else {
            av = make_float4(0.f, 0.f, 0.f, 0.f); aw = av;
        }
        #pragma unroll
        for (int s = 0; s < 4; s++) { bhv[s] = __ldg(&bhp[s]); blv[s] = __ldg(&blp[s]); }
    }

    for (int it = 0; it < KITER; it++) {
        // ---- store current chunk (regs -> smem) ----
        {
            __nv_bfloat162 h0 = __floats2bfloat162_rn(av.x, av.y);
            __nv_bfloat162 h1 = __floats2bfloat162_rn(av.z, av.w);
            __nv_bfloat162 h2 = __floats2bfloat162_rn(aw.x, aw.y);
            __nv_bfloat162 h3 = __floats2bfloat162_rn(aw.z, aw.w);
            __nv_bfloat162 l0 = __floats2bfloat162_rn(av.x - __low2float(h0), av.y - __high2float(h0));
            __nv_bfloat162 l1 = __floats2bfloat162_rn(av.z - __low2float(h1), av.w - __high2float(h1));
            __nv_bfloat162 l2 = __floats2bfloat162_rn(aw.x - __low2float(h2), aw.y - __high2float(h2));
            __nv_bfloat162 l3 = __floats2bfloat162_rn(aw.z - __low2float(h3), aw.w - __high2float(h3));
            int o = arl * PADK + aseg;
            *(uint4*)&Ah[o] = make_uint4(*(uint32_t*)&h0, *(uint32_t*)&h1,
                                         *(uint32_t*)&h2, *(uint32_t*)&h3);
            *(uint4*)&Al[o] = make_uint4(*(uint32_t*)&l0, *(uint32_t*)&l1,
                                         *(uint32_t*)&l2, *(uint32_t*)&l3);
            int ob = brl * PADK + bseg;
            #pragma unroll
            for (int s = 0; s < 4; s++) {
                *(uint4*)&Bh[ob + s * 8] = bhv[s];
                *(uint4*)&Bl[ob + s * 8] = blv[s];
            }
        }
        __syncthreads();

        // ---- issue next chunk's global loads (hide under MMA) ----
        if (it + 1 < KITER) {
            int k0n = (it + 1) * 64;
            if (avalid) {
                av = *(const float4*)&arowp[k0n + aseg];
                aw = *(const float4*)&arowp[k0n + aseg + 4];
            }
            const uint4* bhn = bhp + k0n / 8;
            const uint4* bln = blp + k0n / 8;
            #pragma unroll
            for (int s = 0; s < 4; s++) { bhv[s] = __ldg(&bhn[s]); blv[s] = __ldg(&bln[s]); }
        }

        // ---- MMA: 4 k-steps of 16, ldmatrix fragments ----
        #pragma unroll
        for (int ks = 0; ks < 4; ks++) {
            int kk = ks * 16;
            uint32_t ahf[2][4], alf[2][4];
            #pragma unroll
            for (int mi = 0; mi < 2; mi++) {
                uint32_t off = (uint32_t)(((a_row + mi * 16) * PADK + kk + a_kof) * 2);
                ldsm4(ahf[mi], ah_b + off);
                ldsm4(alf[mi], al_b + off);
            }
            uint32_t bhf[4][2], blf[4][2];
            #pragma unroll
            for (int nj = 0; nj < 2; nj++) {
                uint32_t off = (uint32_t)(((b_row + nj * 16) * PADK + kk + b_kof) * 2);
                uint32_t rh[4], rl[4];
                ldsm4(rh, bh_b + off);
                ldsm4(rl, bl_b + off);
                bhf[2 * nj][0] = rh[0]; bhf[2 * nj][1] = rh[1];
                bhf[2 * nj + 1][0] = rh[2]; bhf[2 * nj + 1][1] = rh[3];
                blf[2 * nj][0] = rl[0]; blf[2 * nj][1] = rl[1];
                blf[2 * nj + 1][0] = rl[2]; blf[2 * nj + 1][1] = rl[3];
            }
            #pragma unroll
            for (int ni = 0; ni < 4; ni++)
                #pragma unroll
                for (int mi = 0; mi < 2; mi++) {
                    mma16816(acc[mi][ni], ahf[mi], bhf[ni][0], bhf[ni][1]);
                    mma16816(acc[mi][ni], ahf[mi], blf[ni][0], blf[ni][1]);
                    mma16816(acc[mi][ni], alf[mi], bhf[ni][0], bhf[ni][1]);
                }
        }
        __syncthreads();
    }

    // ---- epilogue: bias, sum-of-squares, normalize, lrelu, store ----
    #pragma unroll
    for (int mi = 0; mi < 2; mi++) {
        #pragma unroll
        for (int rh = 0; rh < 2; rh++) {
            float ss = 0.f;
            #pragma unroll
            for (int ni = 0; ni < 4; ni++) {
                int col = nbw + ni * 8 + 2 * tig;
                float c0 = acc[mi][ni][rh * 2 + 0] + bs[col];
                float c1 = acc[mi][ni][rh * 2 + 1] + bs[col + 1];
                acc[mi][ni][rh * 2 + 0] = c0;
                acc[mi][ni][rh * 2 + 1] = c1;
                ss += c0 * c0 + c1 * c1;
            }
            ss += __shfl_xor_sync(0xffffffffu, ss, 1);
            ss += __shfl_xor_sync(0xffffffffu, ss, 2);
            if (tig == 0) {
                int row = mw + mi * 16 + rh * 8 + gid;
                ssb[row * 8 + nw] = ss;
            }
        }
    }
    __syncthreads();
    if (tid < 64) {
        const float* p = &ssb[tid * 8];
        float s = p[0] + p[1] + p[2] + p[3] + p[4] + p[5] + p[6] + p[7];
        ivb[tid] = 1.f / fmaxf(sqrtf(s), EPSN);
    }
    __syncthreads();

    #pragma unroll
    for (int mi = 0; mi < 2; mi++) {
        #pragma unroll
        for (int rh = 0; rh < 2; rh++) {
            int rl = mw + mi * 16 + rh * 8 + gid;
            int grow = m0 + rl;
            if (grow >= M) continue;
            int dst = (LAYER == 2) ? g_mlist[grow] : grow;
            float inv = ivb[rl];
            float* crow = C + (size_t)dst * DH;
            #pragma unroll
            for (int ni = 0; ni < 4; ni++) {
                int col = nbw + ni * 8 + 2 * tig;
                float2 v;
                v.x = lrelu(acc[mi][ni][rh * 2 + 0] * inv);
                v.y = lrelu(acc[mi][ni][rh * 2 + 1] * inv);
                *(float2*)&crow[col] = v;
            }
        }
    }
}

// ---------------- layer 3 fused: agg + matvec + normalize ---------------------
__global__ void k_final(const float* __restrict__ W3, const float* __restrict__ b3,
                        float* __restrict__ out) {
    __shared__ float agg[DH];
    __shared__ float red[64];
    int g = blockIdx.x, tid = threadIdx.x;
    int d = g * 100;
    int beg = g_rowptr[d], end = g_rowptr[d + 1];
    float4 acc = make_float4(0.f, 0.f, 0.f, 0.f);
    for (int j = beg; j < end; j++) {
        int s = g_csr[j];
        float4 v = *(const float4*)&g_h2[(size_t)s * DH + tid * 4];
        acc.x += v.x; acc.y += v.y; acc.z += v.z; acc.w += v.w;
    }
    *(float4*)&agg[tid * 4] = acc;
    __syncthreads();
    float o = b3[tid];
    #pragma unroll 8
    for (int k = 0; k < DH; k++) o += agg[k] * W3[k * DOUT + tid];
    red[tid] = o * o;
    __syncthreads();
    #pragma unroll
    for (int s = 32; s > 0; s >>= 1) {
        if (tid < s) red[tid] += red[tid + s];
        __syncthreads();
    }
    float inv = 1.f / fmaxf(sqrtf(red[0]), EPSN);
    out[g * DOUT + tid] = o * inv;
}

// ---------------- launcher ----------------------------------------------------
extern "C" void kernel_launch(void* const* d_in, const int* in_sizes, int n_in,
                              void* d_out, int out_size) {
    const float* x  = (const float*)d_in[0];
    const int*   ei = (const int*)d_in[1];
    const float* W1 = (const float*)d_in[3];
    const float* b1 = (const float*)d_in[4];
    const float* W2 = (const float*)d_in[5];
    const float* b2 = (const float*)d_in[6];
    const float* W3 = (const float*)d_in[7];
    const float* b3 = (const float*)d_in[8];
    float* out = (float*)d_out;

    cudaFuncSetAttribute(k_gemm_mma<1>, cudaFuncAttributeMaxDynamicSharedMemorySize, SM_TOT);
    cudaFuncSetAttribute(k_gemm_mma<2>, cudaFuncAttributeMaxDynamicSharedMemorySize, SM_TOT);

    void *p_deg, *p_mark, *p_mc;
    cudaGetSymbolAddress(&p_deg, g_deg);
    cudaGetSymbolAddress(&p_mark, g_mark);
    cudaGetSymbolAddress(&p_mc, g_mcount);
    cudaMemsetAsync(p_deg, 0, NN * sizeof(int));
    cudaMemsetAsync(p_mark, 0, NN * sizeof(int));
    cudaMemsetAsync(p_mc, 0, sizeof(int));

    const int TB = 256;
    const int nb_prep  = ((NN * DIN / 8) + TB - 1) / TB;   // 3125
    const int nb_edge4 = (NE / 4 + TB - 1) / TB;           // 782
    const int nb_warps = (NN * 32 + TB - 1) / TB;          // 6250
    const int nb_gemm  = (NN + 63) / 64;                   // 782

    k_count_prep<<<nb_prep, TB>>>(ei, x, W1, W2);   // 1
    k_scan1<<<NB, TB>>>();                           // 2
    k_scan23c<<<NB, TB>>>();                         // 3
    k_fill<<<nb_edge4, TB>>>(ei);                    // 4  <- ncu captures this
    k_agg1<<<nb_warps, TB>>>();                      // 5
    k_gemm_mma<1><<<nb_gemm, 512, SM_TOT>>>(b1);     // 6
    k_agg2<<<nb_warps, TB>>>();                      // 7
    k_gemm_mma<2><<<nb_gemm, 512, SM_TOT>>>(b2);     // 8
    k_final<<<NG, DOUT>>>(W3, b3, out);              // 9
}

// round 15
// speedup vs baseline: 1.0918x; 1.0244x over previous
#include <cuda_runtime.h>
#include <cuda_bf16.h>
#include <cuda_fp16.h>
#include <math.h>
#include <stdint.h>

#define NN   50000
#define NE   800000
#define DIN  128
#define DH   256
#define DOUT 64
#define NG   500
#define NEG  0.01f
#define EPSN 1e-12f
#define NB   ((NN + 255) / 256)   // 196 scan blocks

// ---------------- scratch ----------------------------------------------------
__device__ int    g_deg[NN];
__device__ int    g_rowptr[NN + 1];
__device__ int    g_rank[NE];
__device__ int    g_csr[NE];
__device__ int    g_mark[NN];
__device__ int    g_mlist[NN];
__device__ int    g_mcount;
__device__ int    g_bsum[NB];
__device__ __half g_xh[(size_t)NN * DIN];        // fp16 copy of x for gather
__device__ float  g_agg1[(size_t)NN * DIN];
__device__ __half g_h1h[(size_t)NN * DH];        // fp16 h1 (only consumer: agg2)
__device__ float  g_agg2[(size_t)NN * DH];       // compacted rows [mcount]
__device__ float  g_h2[(size_t)NN * DH];
// split weights, transposed [n][k] (col-major B for mma .row.col)
__device__ __nv_bfloat16 g_B1hi[DH * DIN];
__device__ __nv_bfloat16 g_B1lo[DH * DIN];
__device__ __nv_bfloat16 g_B2hi[DH * DH];
__device__ __nv_bfloat16 g_B2lo[DH * DH];

__device__ __forceinline__ float lrelu(float t) { return t >= 0.f ? t : NEG * t; }

__device__ __forceinline__ uint32_t smem_u32(const void* p) {
    uint32_t a;
    asm("{ .reg .u64 t; cvta.to.shared.u64 t, %1; cvt.u32.u64 %0, t; }" : "=r"(a) : "l"(p));
    return a;
}
__device__ __forceinline__ void mma16816(float* d, const uint32_t* a,
                                         uint32_t b0, uint32_t b1) {
    asm volatile(
        "mma.sync.aligned.m16n8k16.row.col.f32.bf16.bf16.f32 "
        "{%0,%1,%2,%3}, {%4,%5,%6,%7}, {%8,%9}, {%0,%1,%2,%3};"
        : "+f"(d[0]), "+f"(d[1]), "+f"(d[2]), "+f"(d[3])
        : "r"(a[0]), "r"(a[1]), "r"(a[2]), "r"(a[3]), "r"(b0), "r"(b1));
}
__device__ __forceinline__ void ldsm4(uint32_t* r, uint32_t addr) {
    asm volatile("ldmatrix.sync.aligned.m8n8.x4.shared.b16 {%0,%1,%2,%3}, [%4];"
                 : "=r"(r[0]), "=r"(r[1]), "=r"(r[2]), "=r"(r[3]) : "r"(addr));
}

// ---------------- preprocessing ----------------------------------------------
__global__ void k_count_prep(const int* __restrict__ ei,
                             const float* __restrict__ x,
                             const float* __restrict__ W1,
                             const float* __restrict__ W2) {
    int t = blockIdx.x * blockDim.x + threadIdx.x;
    {   // fp16 conversion: 8 elements per thread, covers all 6.4M exactly
        size_t c0 = (size_t)t * 8;
        if (c0 < (size_t)NN * DIN) {
            float4 a = __ldg((const float4*)&x[c0]);
            float4 b = __ldg((const float4*)&x[c0 + 4]);
            __half2 h0 = __floats2half2_rn(a.x, a.y);
            __half2 h1 = __floats2half2_rn(a.z, a.w);
            __half2 h2 = __floats2half2_rn(b.x, b.y);
            __half2 h3 = __floats2half2_rn(b.z, b.w);
            *(uint4*)&g_xh[c0] = make_uint4(*(uint32_t*)&h0, *(uint32_t*)&h1,
                                            *(uint32_t*)&h2, *(uint32_t*)&h3);
        }
    }
    int e0 = t * 4;
    if (e0 < NE) {
        int4 s4 = *(const int4*)&ei[e0];
        int4 d4 = *(const int4*)&ei[NE + e0];
        int r0 = atomicAdd(&g_deg[d4.x], 1);
        int r1 = atomicAdd(&g_deg[d4.y], 1);
        int r2 = atomicAdd(&g_deg[d4.z], 1);
        int r3 = atomicAdd(&g_deg[d4.w], 1);
        *(int4*)&g_rank[e0] = make_int4(r0, r1, r2, r3);
        if (d4.x % 100 == 0) g_mark[s4.x] = 1;
        if (d4.y % 100 == 0) g_mark[s4.y] = 1;
        if (d4.z % 100 == 0) g_mark[s4.z] = 1;
        if (d4.w % 100 == 0) g_mark[s4.w] = 1;
    }
    if (t < DIN * DH) {           // W1: [k][n]
        int k = t / DH, n = t % DH;
        float f = W1[t];
        __nv_bfloat16 h = __float2bfloat16(f);
        g_B1hi[n * DIN + k] = h;
        g_B1lo[n * DIN + k] = __float2bfloat16(f - __bfloat162float(h));
    }
    if (t < DH * DH) {            // W2: [k][n]
        int k = t / DH, n = t % DH;
        float f = W2[t];
        __nv_bfloat16 h = __float2bfloat16(f);
        g_B2hi[n * DH + k] = h;
        g_B2lo[n * DH + k] = __float2bfloat16(f - __bfloat162float(h));
    }
}

__device__ __forceinline__ int block_scan_inc(int v, int tid, int* ws) {
    int lane = tid & 31, wd = tid >> 5;
    int x = v;
    #pragma unroll
    for (int o = 1; o < 32; o <<= 1) {
        int t = __shfl_up_sync(0xffffffffu, x, o);
        if (lane >= o) x += t;
    }
    if (lane == 31) ws[wd] = x;
    __syncthreads();
    if (tid < 8) {
        int s = ws[tid];
        #pragma unroll
        for (int o = 1; o < 8; o <<= 1) {
            int t = __shfl_up_sync(0xffu, s, o);
            if (tid >= o) s += t;
        }
        ws[tid] = s;
    }
    __syncthreads();
    return x + (wd ? ws[wd - 1] : 0);
}

__global__ void k_scan1() {
    __shared__ int ws[8];
    int tid = threadIdx.x;
    int gi = blockIdx.x * 256 + tid;
    int v = (gi < NN) ? g_deg[gi] : 0;
    int inc = block_scan_inc(v, tid, ws);
    if (gi < NN) g_rowptr[gi + 1] = inc;
    if (tid == 255) g_bsum[blockIdx.x] = inc;
}

__global__ void k_scan23c() {
    __shared__ int ws[8];
    __shared__ int s_off;
    int tid = threadIdx.x, bid = blockIdx.x;
    int v2 = (tid < NB) ? g_bsum[tid] : 0;
    int inc2 = block_scan_inc(v2, tid, ws);
    if (tid == bid) s_off = inc2 - v2;   // exclusive prefix for this block
    __syncthreads();
    int gi = bid * 256 + tid;
    if (gi >= NN) return;
    int inc = g_rowptr[gi + 1] + s_off;
    g_rowptr[gi + 1] = inc;
    if (gi == 0) g_rowptr[0] = 0;
    if (g_mark[gi]) {
        int p = atomicAdd(&g_mcount, 1);
        g_mlist[p] = gi;
    }
}

// atomic-free scatter: position = rowptr[dst] + precomputed rank
__global__ void k_fill(const int* __restrict__ ei) {
    int t = blockIdx.x * blockDim.x + threadIdx.x;
    int e0 = t * 4;
    if (e0 >= NE) return;
    int4 s4 = *(const int4*)&ei[e0];
    int4 d4 = *(const int4*)&ei[NE + e0];
    int4 r4 = *(const int4*)&g_rank[e0];
    g_csr[g_rowptr[d4.x] + r4.x] = s4.x;
    g_csr[g_rowptr[d4.y] + r4.y] = s4.y;
    g_csr[g_rowptr[d4.z] + r4.z] = s4.z;
    g_csr[g_rowptr[d4.w] + r4.w] = s4.w;
}

// ---------------- aggregation (warp per node, fp16 gather, fp32 accumulate) ---
__global__ void k_agg1() {
    int w    = (blockIdx.x * blockDim.x + threadIdx.x) >> 5;
    int lane = threadIdx.x & 31;
    if (w >= NN) return;
    int beg = g_rowptr[w], end = g_rowptr[w + 1];
    float4 acc = make_float4(0.f, 0.f, 0.f, 0.f);
    int j = beg;
    for (; j + 4 <= end; j += 4) {
        int s0 = g_csr[j], s1 = g_csr[j + 1], s2 = g_csr[j + 2], s3 = g_csr[j + 3];
        uint2 u0 = __ldg((const uint2*)&g_xh[(size_t)s0 * DIN + lane * 4]);
        uint2 u1 = __ldg((const uint2*)&g_xh[(size_t)s1 * DIN + lane * 4]);
        uint2 u2 = __ldg((const uint2*)&g_xh[(size_t)s2 * DIN + lane * 4]);
        uint2 u3 = __ldg((const uint2*)&g_xh[(size_t)s3 * DIN + lane * 4]);
        float2 a0 = __half22float2(*(__half2*)&u0.x), b0 = __half22float2(*(__half2*)&u0.y);
        float2 a1 = __half22float2(*(__half2*)&u1.x), b1 = __half22float2(*(__half2*)&u1.y);
        float2 a2 = __half22float2(*(__half2*)&u2.x), b2 = __half22float2(*(__half2*)&u2.y);
        float2 a3 = __half22float2(*(__half2*)&u3.x), b3 = __half22float2(*(__half2*)&u3.y);
        acc.x += a0.x + a1.x + a2.x + a3.x;
        acc.y += a0.y + a1.y + a2.y + a3.y;
        acc.z += b0.x + b1.x + b2.x + b3.x;
        acc.w += b0.y + b1.y + b2.y + b3.y;
    }
    for (; j < end; j++) {
        int s = g_csr[j];
        uint2 u = __ldg((const uint2*)&g_xh[(size_t)s * DIN + lane * 4]);
        float2 a = __half22float2(*(__half2*)&u.x), b = __half22float2(*(__half2*)&u.y);
        acc.x += a.x; acc.y += a.y; acc.z += b.x; acc.w += b.y;
    }
    *(float4*)&g_agg1[(size_t)w * DIN + lane * 4] = acc;
}

// agg2: fp16 h1 gather (one uint4 = 8 halves per lane per edge), fp32 accumulate
__global__ void k_agg2() {
    int w    = (blockIdx.x * blockDim.x + threadIdx.x) >> 5;
    int lane = threadIdx.x & 31;
    if (w >= g_mcount) return;
    int v   = g_mlist[w];
    int beg = g_rowptr[v], end = g_rowptr[v + 1];
    float a[8];
    #pragma unroll
    for (int q = 0; q < 8; q++) a[q] = 0.f;
    int j = beg;
    for (; j + 2 <= end; j += 2) {
        int s0 = g_csr[j], s1 = g_csr[j + 1];
        uint4 u0 = __ldg((const uint4*)&g_h1h[(size_t)s0 * DH + lane * 8]);
        uint4 u1 = __ldg((const uint4*)&g_h1h[(size_t)s1 * DH + lane * 8]);
        float2 p;
        p = __half22float2(*(__half2*)&u0.x); a[0] += p.x; a[1] += p.y;
        p = __half22float2(*(__half2*)&u0.y); a[2] += p.x; a[3] += p.y;
        p = __half22float2(*(__half2*)&u0.z); a[4] += p.x; a[5] += p.y;
        p = __half22float2(*(__half2*)&u0.w); a[6] += p.x; a[7] += p.y;
        p = __half22float2(*(__half2*)&u1.x); a[0] += p.x; a[1] += p.y;
        p = __half22float2(*(__half2*)&u1.y); a[2] += p.x; a[3] += p.y;
        p = __half22float2(*(__half2*)&u1.z); a[4] += p.x; a[5] += p.y;
        p = __half22float2(*(__half2*)&u1.w); a[6] += p.x; a[7] += p.y;
    }
    for (; j < end; j++) {
        int s = g_csr[j];
        uint4 u = __ldg((const uint4*)&g_h1h[(size_t)s * DH + lane * 8]);
        float2 p;
        p = __half22float2(*(__half2*)&u.x); a[0] += p.x; a[1] += p.y;
        p = __half22float2(*(__half2*)&u.y); a[2] += p.x; a[3] += p.y;
        p = __half22float2(*(__half2*)&u.z); a[4] += p.x; a[5] += p.y;
        p = __half22float2(*(__half2*)&u.w); a[6] += p.x; a[7] += p.y;
    }
    float* o = &g_agg2[(size_t)w * DH + lane * 8];
    *(float4*)&o[0] = make_float4(a[0], a[1], a[2], a[3]);
    *(float4*)&o[4] = make_float4(a[4], a[5], a[6], a[7]);
}

// ---------------- mma.sync split-bf16 GEMM + fused bias/L2norm/leakyrelu ------
// 512 threads = 16 warps (2m x 8n), tile 64m x 256n, K chunks of 64,
// register-prefetch software pipeline on A/B staging.
#define PADK 72
#define SM_AHI  0
#define SM_ALO  (SM_AHI + 64 * PADK * 2)
#define SM_BHI  (SM_ALO + 64 * PADK * 2)
#define SM_BLO  (SM_BHI + 256 * PADK * 2)
#define SM_BIAS (SM_BLO + 256 * PADK * 2)
#define SM_SS   (SM_BIAS + DH * 4)
#define SM_INV  (SM_SS + 64 * 8 * 4)
#define SM_TOT  (SM_INV + 64 * 4)

template <int LAYER>
__global__ void __launch_bounds__(512, 1)
k_gemm_mma(const float* __restrict__ bias) {
    constexpr int K     = (LAYER == 1) ? DIN : DH;
    constexpr int KITER = K / 64;
    extern __shared__ char smem[];
    __nv_bfloat16* Ah = (__nv_bfloat16*)(smem + SM_AHI);
    __nv_bfloat16* Al = (__nv_bfloat16*)(smem + SM_ALO);
    __nv_bfloat16* Bh = (__nv_bfloat16*)(smem + SM_BHI);
    __nv_bfloat16* Bl = (__nv_bfloat16*)(smem + SM_BLO);
    float* bs  = (float*)(smem + SM_BIAS);
    float* ssb = (float*)(smem + SM_SS);
    float* ivb = (float*)(smem + SM_INV);

    int M = (LAYER == 1) ? NN : g_mcount;
    int m0 = blockIdx.x * 64;
    if (m0 >= M) return;

    int tid = threadIdx.x, wid = tid >> 5, lane = tid & 31;
    int gid = lane >> 2, tig = lane & 3;
    int mw = (wid >> 3) * 32;       // 2 m warp-rows
    int nw = wid & 7;               // 8 n warps
    int nbw = nw * 32;

    if (tid < DH) bs[tid] = bias[tid];

    const float* A = (LAYER == 1) ? g_agg1 : g_agg2;
    const __nv_bfloat16* Bhig = (LAYER == 1) ? g_B1hi : g_B2hi;
    const __nv_bfloat16* Blog = (LAYER == 1) ? g_B1lo : g_B2lo;

    // A staging map: thread -> row tid>>3 (0..63), seg (tid&7)*8
    int  arl    = tid >> 3;
    int  aseg   = (tid & 7) * 8;
    int  agrow  = m0 + arl;
    bool avalid = agrow < M;
    const float* arowp = A + (size_t)(avalid ? agrow : 0) * K;
    // B staging map: thread -> row tid>>1 (0..255), half (tid&1)*32
    int brl  = tid >> 1;
    int bseg = (tid & 1) * 32;
    const uint4* bhp = (const uint4*)(Bhig + (size_t)brl * K + bseg);
    const uint4* blp = (const uint4*)(Blog + (size_t)brl * K + bseg);

    // ldmatrix lane maps
    uint32_t ah_b = smem_u32(Ah), al_b = smem_u32(Al);
    uint32_t bh_b = smem_u32(Bh), bl_b = smem_u32(Bl);
    int a_row = mw + (lane & 7) + ((lane >> 3) & 1) * 8;   // + mi*16
    int a_kof = (lane >> 4) * 8;
    int b_row = nbw + (lane & 7) + ((lane >> 4) & 1) * 8;  // + nj*16
    int b_kof = ((lane >> 3) & 1) * 8;

    float acc[2][4][4];
    #pragma unroll
    for (int mi = 0; mi < 2; mi++)
        #pragma unroll
        for (int ni = 0; ni < 4; ni++)
            #pragma unroll
            for (int q = 0; q < 4; q++) acc[mi][ni][q] = 0.f;

    // prefetch registers
    float4 av, aw;
    uint4  bhv[4], blv[4];
    {
        if (avalid) {
            av = *(const float4*)&arowp[aseg];
            aw = *(const float4*)&arowp[aseg + 4];
        } else {
            av = make_float4(0.f, 0.f, 0.f, 0.f); aw = av;
        }
        #pragma unroll
        for (int s = 0; s < 4; s++) { bhv[s] = __ldg(&bhp[s]); blv[s] = __ldg(&blp[s]); }
    }

    for (int it = 0; it < KITER; it++) {
        // ---- store current chunk (regs -> smem) ----
        {
            __nv_bfloat162 h0 = __floats2bfloat162_rn(av.x, av.y);
            __nv_bfloat162 h1 = __floats2bfloat162_rn(av.z, av.w);
            __nv_bfloat162 h2 = __floats2bfloat162_rn(aw.x, aw.y);
            __nv_bfloat162 h3 = __floats2bfloat162_rn(aw.z, aw.w);
            __nv_bfloat162 l0 = __floats2bfloat162_rn(av.x - __low2float(h0), av.y - __high2float(h0));
            __nv_bfloat162 l1 = __floats2bfloat162_rn(av.z - __low2float(h1), av.w - __high2float(h1));
            __nv_bfloat162 l2 = __floats2bfloat162_rn(aw.x - __low2float(h2), aw.y - __high2float(h2));
            __nv_bfloat162 l3 = __floats2bfloat162_rn(aw.z - __low2float(h3), aw.w - __high2float(h3));
            int o = arl * PADK + aseg;
            *(uint4*)&Ah[o] = make_uint4(*(uint32_t*)&h0, *(uint32_t*)&h1,
                                         *(uint32_t*)&h2, *(uint32_t*)&h3);
            *(uint4*)&Al[o] = make_uint4(*(uint32_t*)&l0, *(uint32_t*)&l1,
                                         *(uint32_t*)&l2, *(uint32_t*)&l3);
            int ob = brl * PADK + bseg;
            #pragma unroll
            for (int s = 0; s < 4; s++) {
                *(uint4*)&Bh[ob + s * 8] = bhv[s];
                *(uint4*)&Bl[ob + s * 8] = blv[s];
            }
        }
        __syncthreads();

        // ---- issue next chunk's global loads (hide under MMA) ----
        if (it + 1 < KITER) {
            int k0n = (it + 1) * 64;
            if (avalid) {
                av = *(const float4*)&arowp[k0n + aseg];
                aw = *(const float4*)&arowp[k0n + aseg + 4];
            }
            const uint4* bhn = bhp + k0n / 8;
            const uint4* bln = blp + k0n / 8;
            #pragma unroll
            for (int s = 0; s < 4; s++) { bhv[s] = __ldg(&bhn[s]); blv[s] = __ldg(&bln[s]); }
        }

        // ---- MMA: 4 k-steps of 16, ldmatrix fragments ----
        #pragma unroll
        for (int ks = 0; ks < 4; ks++) {
            int kk = ks * 16;
            uint32_t ahf[2][4], alf[2][4];
            #pragma unroll
            for (int mi = 0; mi < 2; mi++) {
                uint32_t off = (uint32_t)(((a_row + mi * 16) * PADK + kk + a_kof) * 2);
                ldsm4(ahf[mi], ah_b + off);
                ldsm4(alf[mi], al_b + off);
            }
            uint32_t bhf[4][2], blf[4][2];
            #pragma unroll
            for (int nj = 0; nj < 2; nj++) {
                uint32_t off = (uint32_t)(((b_row + nj * 16) * PADK + kk + b_kof) * 2);
                uint32_t rh[4], rl[4];
                ldsm4(rh, bh_b + off);
                ldsm4(rl, bl_b + off);
                bhf[2 * nj][0] = rh[0]; bhf[2 * nj][1] = rh[1];
                bhf[2 * nj + 1][0] = rh[2]; bhf[2 * nj + 1][1] = rh[3];
                blf[2 * nj][0] = rl[0]; blf[2 * nj][1] = rl[1];
                blf[2 * nj + 1][0] = rl[2]; blf[2 * nj + 1][1] = rl[3];
            }
            #pragma unroll
            for (int ni = 0; ni < 4; ni++)
                #pragma unroll
                for (int mi = 0; mi < 2; mi++) {
                    mma16816(acc[mi][ni], ahf[mi], bhf[ni][0], bhf[ni][1]);
                    mma16816(acc[mi][ni], ahf[mi], blf[ni][0], blf[ni][1]);
                    mma16816(acc[mi][ni], alf[mi], bhf[ni][0], bhf[ni][1]);
                }
        }
        __syncthreads();
    }

    // ---- epilogue: bias, sum-of-squares, normalize, lrelu, store ----
    #pragma unroll
    for (int mi = 0; mi < 2; mi++) {
        #pragma unroll
        for (int rh = 0; rh < 2; rh++) {
            float ss = 0.f;
            #pragma unroll
            for (int ni = 0; ni < 4; ni++) {
                int col = nbw + ni * 8 + 2 * tig;
                float c0 = acc[mi][ni][rh * 2 + 0] + bs[col];
                float c1 = acc[mi][ni][rh * 2 + 1] + bs[col + 1];
                acc[mi][ni][rh * 2 + 0] = c0;
                acc[mi][ni][rh * 2 + 1] = c1;
                ss += c0 * c0 + c1 * c1;
            }
            ss += __shfl_xor_sync(0xffffffffu, ss, 1);
            ss += __shfl_xor_sync(0xffffffffu, ss, 2);
            if (tig == 0) {
                int row = mw + mi * 16 + rh * 8 + gid;
                ssb[row * 8 + nw] = ss;
            }
        }
    }
    __syncthreads();
    if (tid < 64) {
        const float* p = &ssb[tid * 8];
        float s = p[0] + p[1] + p[2] + p[3] + p[4] + p[5] + p[6] + p[7];
        ivb[tid] = 1.f / fmaxf(sqrtf(s), EPSN);
    }
    __syncthreads();

    #pragma unroll
    for (int mi = 0; mi < 2; mi++) {
        #pragma unroll
        for (int rh = 0; rh < 2; rh++) {
            int rl = mw + mi * 16 + rh * 8 + gid;
            int grow = m0 + rl;
            if (grow >= M) continue;
            float inv = ivb[rl];
            if (LAYER == 1) {
                __half* crow = g_h1h + (size_t)grow * DH;
                #pragma unroll
                for (int ni = 0; ni < 4; ni++) {
                    int col = nbw + ni * 8 + 2 * tig;
                    float vx = lrelu(acc[mi][ni][rh * 2 + 0] * inv);
                    float vy = lrelu(acc[mi][ni][rh * 2 + 1] * inv);
                    __half2 hv = __floats2half2_rn(vx, vy);
                    *(__half2*)&crow[col] = hv;
                }
            } else {
                int dst = g_mlist[grow];
                float* crow = g_h2 + (size_t)dst * DH;
                #pragma unroll
                for (int ni = 0; ni < 4; ni++) {
                    int col = nbw + ni * 8 + 2 * tig;
                    float2 v;
                    v.x = lrelu(acc[mi][ni][rh * 2 + 0] * inv);
                    v.y = lrelu(acc[mi][ni][rh * 2 + 1] * inv);
                    *(float2*)&crow[col] = v;
                }
            }
        }
    }
}

// ---------------- layer 3 fused: agg + matvec + normalize ---------------------
__global__ void k_final(const float* __restrict__ W3, const float* __restrict__ b3,
                        float* __restrict__ out) {
    __shared__ float agg[DH];
    __shared__ float red[64];
    int g = blockIdx.x, tid = threadIdx.x;
    int d = g * 100;
    int beg = g_rowptr[d], end = g_rowptr[d + 1];
    float4 acc = make_float4(0.f, 0.f, 0.f, 0.f);
    for (int j = beg; j < end; j++) {
        int s = g_csr[j];
        float4 v = *(const float4*)&g_h2[(size_t)s * DH + tid * 4];
        acc.x += v.x; acc.y += v.y; acc.z += v.z; acc.w += v.w;
    }
    *(float4*)&agg[tid * 4] = acc;
    __syncthreads();
    float o = b3[tid];
    #pragma unroll 8
    for (int k = 0; k < DH; k++) o += agg[k] * W3[k * DOUT + tid];
    red[tid] = o * o;
    __syncthreads();
    #pragma unroll
    for (int s = 32; s > 0; s >>= 1) {
        if (tid < s) red[tid] += red[tid + s];
        __syncthreads();
    }
    float inv = 1.f / fmaxf(sqrtf(red[0]), EPSN);
    out[g * DOUT + tid] = o * inv;
}

// ---------------- launcher ----------------------------------------------------
extern "C" void kernel_launch(void* const* d_in, const int* in_sizes, int n_in,
                              void* d_out, int out_size) {
    const float* x  = (const float*)d_in[0];
    const int*   ei = (const int*)d_in[1];
    const float* W1 = (const float*)d_in[3];
    const float* b1 = (const float*)d_in[4];
    const float* W2 = (const float*)d_in[5];
    const float* b2 = (const float*)d_in[6];
    const float* W3 = (const float*)d_in[7];
    const float* b3 = (const float*)d_in[8];
    float* out = (float*)d_out;

    cudaFuncSetAttribute(k_gemm_mma<1>, cudaFuncAttributeMaxDynamicSharedMemorySize, SM_TOT);
    cudaFuncSetAttribute(k_gemm_mma<2>, cudaFuncAttributeMaxDynamicSharedMemorySize, SM_TOT);

    void *p_deg, *p_mark, *p_mc;
    cudaGetSymbolAddress(&p_deg, g_deg);
    cudaGetSymbolAddress(&p_mark, g_mark);
    cudaGetSymbolAddress(&p_mc, g_mcount);
    cudaMemsetAsync(p_deg, 0, NN * sizeof(int));
    cudaMemsetAsync(p_mark, 0, NN * sizeof(int));
    cudaMemsetAsync(p_mc, 0, sizeof(int));

    const int TB = 256;
    const int nb_prep  = ((NN * DIN / 8) + TB - 1) / TB;   // 3125
    const int nb_edge4 = (NE / 4 + TB - 1) / TB;           // 782
    const int nb_warps = (NN * 32 + TB - 1) / TB;          // 6250
    const int nb_gemm  = (NN + 63) / 64;                   // 782

    k_count_prep<<<nb_prep, TB>>>(ei, x, W1, W2);   // 1
    k_scan1<<<NB, TB>>>();                           // 2
    k_scan23c<<<NB, TB>>>();                         // 3
    k_fill<<<nb_edge4, TB>>>(ei);                    // 4  <- ncu captures this
    k_agg1<<<nb_warps, TB>>>();                      // 5
    k_gemm_mma<1><<<nb_gemm, 512, SM_TOT>>>(b1);     // 6
    k_agg2<<<nb_warps, TB>>>();                      // 7
    k_gemm_mma<2><<<nb_gemm, 512, SM_TOT>>>(b2);     // 8
    k_final<<<NG, DOUT>>>(W3, b3, out);              // 9
}

// round 17
// speedup vs baseline: 1.3547x; 1.2408x over previous
#include <cuda_runtime.h>
#include <cuda_fp16.h>
#include <math.h>
#include <stdint.h>

#define NN   50000
#define NE   800000
#define DIN  128
#define DH   256
#define DOUT 64
#define NG   500
#define NEG  0.01f
#define EPSN 1e-12f
#define NB   ((NN + 255) / 256)   // 196 scan blocks

// ---------------- scratch ----------------------------------------------------
__device__ int    g_deg[NN];
__device__ int    g_rowptr[NN + 1];
__device__ int    g_rank[NE];
__device__ int    g_csr[NE];
__device__ int    g_mark[NN];
__device__ int    g_mlist[NN];
__device__ int    g_mcount;
__device__ int    g_bsum[NB];
__device__ __half g_xh[(size_t)NN * DIN];        // fp16 copy of x for gather
__device__ __half g_agg1[(size_t)NN * DIN];      // fp16 (GEMM A operand anyway)
__device__ __half g_h1h[(size_t)NN * DH];        // fp16 h1 (only consumer: agg2)
__device__ __half g_agg2[(size_t)NN * DH];       // fp16, compacted rows [mcount]
__device__ float  g_h2[(size_t)NN * DH];
// fp16 weights, transposed [n][k] (col-major B for mma .row.col)
__device__ __half g_B1h[DH * DIN];
__device__ __half g_B2h[DH * DH];

__device__ __forceinline__ float lrelu(float t) { return t >= 0.f ? t : NEG * t; }

__device__ __forceinline__ uint32_t smem_u32(const void* p) {
    uint32_t a;
    asm("{ .reg .u64 t; cvta.to.shared.u64 t, %1; cvt.u32.u64 %0, t; }" : "=r"(a) : "l"(p));
    return a;
}
__device__ __forceinline__ void mma16816f(float* d, const uint32_t* a,
                                          uint32_t b0, uint32_t b1) {
    asm volatile(
        "mma.sync.aligned.m16n8k16.row.col.f32.f16.f16.f32 "
        "{%0,%1,%2,%3}, {%4,%5,%6,%7}, {%8,%9}, {%0,%1,%2,%3};"
        : "+f"(d[0]), "+f"(d[1]), "+f"(d[2]), "+f"(d[3])
        : "r"(a[0]), "r"(a[1]), "r"(a[2]), "r"(a[3]), "r"(b0), "r"(b1));
}
__device__ __forceinline__ void ldsm4(uint32_t* r, uint32_t addr) {
    asm volatile("ldmatrix.sync.aligned.m8n8.x4.shared.b16 {%0,%1,%2,%3}, [%4];"
                 : "=r"(r[0]), "=r"(r[1]), "=r"(r[2]), "=r"(r[3]) : "r"(addr));
}

// ---------------- preprocessing ----------------------------------------------
__global__ void k_count_prep(const int* __restrict__ ei,
                             const float* __restrict__ x,
                             const float* __restrict__ W1,
                             const float* __restrict__ W2) {
    int t = blockIdx.x * blockDim.x + threadIdx.x;
    {   // fp16 conversion: 8 elements per thread, covers all 6.4M exactly
        size_t c0 = (size_t)t * 8;
        if (c0 < (size_t)NN * DIN) {
            float4 a = __ldg((const float4*)&x[c0]);
            float4 b = __ldg((const float4*)&x[c0 + 4]);
            __half2 h0 = __floats2half2_rn(a.x, a.y);
            __half2 h1 = __floats2half2_rn(a.z, a.w);
            __half2 h2 = __floats2half2_rn(b.x, b.y);
            __half2 h3 = __floats2half2_rn(b.z, b.w);
            *(uint4*)&g_xh[c0] = make_uint4(*(uint32_t*)&h0, *(uint32_t*)&h1,
                                            *(uint32_t*)&h2, *(uint32_t*)&h3);
        }
    }
    int e0 = t * 4;
    if (e0 < NE) {
        int4 s4 = *(const int4*)&ei[e0];
        int4 d4 = *(const int4*)&ei[NE + e0];
        int r0 = atomicAdd(&g_deg[d4.x], 1);
        int r1 = atomicAdd(&g_deg[d4.y], 1);
        int r2 = atomicAdd(&g_deg[d4.z], 1);
        int r3 = atomicAdd(&g_deg[d4.w], 1);
        *(int4*)&g_rank[e0] = make_int4(r0, r1, r2, r3);
        if (d4.x % 100 == 0) g_mark[s4.x] = 1;
        if (d4.y % 100 == 0) g_mark[s4.y] = 1;
        if (d4.z % 100 == 0) g_mark[s4.z] = 1;
        if (d4.w % 100 == 0) g_mark[s4.w] = 1;
    }
    if (t < DIN * DH) {           // W1: [k][n] -> fp16 [n][k]
        int k = t / DH, n = t % DH;
        g_B1h[n * DIN + k] = __float2half(W1[t]);
    }
    if (t < DH * DH) {            // W2: [k][n] -> fp16 [n][k]
        int k = t / DH, n = t % DH;
        g_B2h[n * DH + k] = __float2half(W2[t]);
    }
}

__device__ __forceinline__ int block_scan_inc(int v, int tid, int* ws) {
    int lane = tid & 31, wd = tid >> 5;
    int x = v;
    #pragma unroll
    for (int o = 1; o < 32; o <<= 1) {
        int t = __shfl_up_sync(0xffffffffu, x, o);
        if (lane >= o) x += t;
    }
    if (lane == 31) ws[wd] = x;
    __syncthreads();
    if (tid < 8) {
        int s = ws[tid];
        #pragma unroll
        for (int o = 1; o < 8; o <<= 1) {
            int t = __shfl_up_sync(0xffu, s, o);
            if (tid >= o) s += t;
        }
        ws[tid] = s;
    }
    __syncthreads();
    return x + (wd ? ws[wd - 1] : 0);
}

__global__ void k_scan1() {
    __shared__ int ws[8];
    int tid = threadIdx.x;
    int gi = blockIdx.x * 256 + tid;
    int v = (gi < NN) ? g_deg[gi] : 0;
    int inc = block_scan_inc(v, tid, ws);
    if (gi < NN) g_rowptr[gi + 1] = inc;
    if (tid == 255) g_bsum[blockIdx.x] = inc;
}

__global__ void k_scan23c() {
    __shared__ int ws[8];
    __shared__ int s_off;
    int tid = threadIdx.x, bid = blockIdx.x;
    int v2 = (tid < NB) ? g_bsum[tid] : 0;
    int inc2 = block_scan_inc(v2, tid, ws);
    if (tid == bid) s_off = inc2 - v2;
    __syncthreads();
    int gi = bid * 256 + tid;
    if (gi >= NN) return;
    int inc = g_rowptr[gi + 1] + s_off;
    g_rowptr[gi + 1] = inc;
    if (gi == 0) g_rowptr[0] = 0;
    if (g_mark[gi]) {
        int p = atomicAdd(&g_mcount, 1);
        g_mlist[p] = gi;
    }
}

// atomic-free scatter: position = rowptr[dst] + precomputed rank
__global__ void k_fill(const int* __restrict__ ei) {
    int t = blockIdx.x * blockDim.x + threadIdx.x;
    int e0 = t * 4;
    if (e0 >= NE) return;
    int4 s4 = *(const int4*)&ei[e0];
    int4 d4 = *(const int4*)&ei[NE + e0];
    int4 r4 = *(const int4*)&g_rank[e0];
    g_csr[g_rowptr[d4.x] + r4.x] = s4.x;
    g_csr[g_rowptr[d4.y] + r4.y] = s4.y;
    g_csr[g_rowptr[d4.z] + r4.z] = s4.z;
    g_csr[g_rowptr[d4.w] + r4.w] = s4.w;
}

// ---------------- aggregation (warp per node, fp16 gather, fp32 accumulate) ---
__global__ void k_agg1() {
    int w    = (blockIdx.x * blockDim.x + threadIdx.x) >> 5;
    int lane = threadIdx.x & 31;
    if (w >= NN) return;
    int beg = g_rowptr[w], end = g_rowptr[w + 1];
    float4 acc = make_float4(0.f, 0.f, 0.f, 0.f);
    int j = beg;
    for (; j + 4 <= end; j += 4) {
        int s0 = g_csr[j], s1 = g_csr[j + 1], s2 = g_csr[j + 2], s3 = g_csr[j + 3];
        uint2 u0 = __ldg((const uint2*)&g_xh[(size_t)s0 * DIN + lane * 4]);
        uint2 u1 = __ldg((const uint2*)&g_xh[(size_t)s1 * DIN + lane * 4]);
        uint2 u2 = __ldg((const uint2*)&g_xh[(size_t)s2 * DIN + lane * 4]);
        uint2 u3 = __ldg((const uint2*)&g_xh[(size_t)s3 * DIN + lane * 4]);
        float2 a0 = __half22float2(*(__half2*)&u0.x), b0 = __half22float2(*(__half2*)&u0.y);
        float2 a1 = __half22float2(*(__half2*)&u1.x), b1 = __half22float2(*(__half2*)&u1.y);
        float2 a2 = __half22float2(*(__half2*)&u2.x), b2 = __half22float2(*(__half2*)&u2.y);
        float2 a3 = __half22float2(*(__half2*)&u3.x), b3 = __half22float2(*(__half2*)&u3.y);
        acc.x += a0.x + a1.x + a2.x + a3.x;
        acc.y += a0.y + a1.y + a2.y + a3.y;
        acc.z += b0.x + b1.x + b2.x + b3.x;
        acc.w += b0.y + b1.y + b2.y + b3.y;
    }
    for (; j < end; j++) {
        int s = g_csr[j];
        uint2 u = __ldg((const uint2*)&g_xh[(size_t)s * DIN + lane * 4]);
        float2 a = __half22float2(*(__half2*)&u.x), b = __half22float2(*(__half2*)&u.y);
        acc.x += a.x; acc.y += a.y; acc.z += b.x; acc.w += b.y;
    }
    __half2 o01 = __floats2half2_rn(acc.x, acc.y);
    __half2 o23 = __floats2half2_rn(acc.z, acc.w);
    *(uint2*)&g_agg1[(size_t)w * DIN + lane * 4] = make_uint2(*(uint32_t*)&o01, *(uint32_t*)&o23);
}

// agg2: fp16 h1 gather, fp32 accumulate, fp16 compacted output
__global__ void k_agg2() {
    int w    = (blockIdx.x * blockDim.x + threadIdx.x) >> 5;
    int lane = threadIdx.x & 31;
    if (w >= g_mcount) return;
    int v   = g_mlist[w];
    int beg = g_rowptr[v], end = g_rowptr[v + 1];
    float a[8];
    #pragma unroll
    for (int q = 0; q < 8; q++) a[q] = 0.f;
    int j = beg;
    for (; j + 2 <= end; j += 2) {
        int s0 = g_csr[j], s1 = g_csr[j + 1];
        uint4 u0 = __ldg((const uint4*)&g_h1h[(size_t)s0 * DH + lane * 8]);
        uint4 u1 = __ldg((const uint4*)&g_h1h[(size_t)s1 * DH + lane * 8]);
        float2 p;
        p = __half22float2(*(__half2*)&u0.x); a[0] += p.x; a[1] += p.y;
        p = __half22float2(*(__half2*)&u0.y); a[2] += p.x; a[3] += p.y;
        p = __half22float2(*(__half2*)&u0.z); a[4] += p.x; a[5] += p.y;
        p = __half22float2(*(__half2*)&u0.w); a[6] += p.x; a[7] += p.y;
        p = __half22float2(*(__half2*)&u1.x); a[0] += p.x; a[1] += p.y;
        p = __half22float2(*(__half2*)&u1.y); a[2] += p.x; a[3] += p.y;
        p = __half22float2(*(__half2*)&u1.z); a[4] += p.x; a[5] += p.y;
        p = __half22float2(*(__half2*)&u1.w); a[6] += p.x; a[7] += p.y;
    }
    for (; j < end; j++) {
        int s = g_csr[j];
        uint4 u = __ldg((const uint4*)&g_h1h[(size_t)s * DH + lane * 8]);
        float2 p;
        p = __half22float2(*(__half2*)&u.x); a[0] += p.x; a[1] += p.y;
        p = __half22float2(*(__half2*)&u.y); a[2] += p.x; a[3] += p.y;
        p = __half22float2(*(__half2*)&u.z); a[4] += p.x; a[5] += p.y;
        p = __half22float2(*(__half2*)&u.w); a[6] += p.x; a[7] += p.y;
    }
    __half2 h0 = __floats2half2_rn(a[0], a[1]);
    __half2 h1 = __floats2half2_rn(a[2], a[3]);
    __half2 h2 = __floats2half2_rn(a[4], a[5]);
    __half2 h3 = __floats2half2_rn(a[6], a[7]);
    *(uint4*)&g_agg2[(size_t)w * DH + lane * 8] =
        make_uint4(*(uint32_t*)&h0, *(uint32_t*)&h1, *(uint32_t*)&h2, *(uint32_t*)&h3);
}

// ---------------- single-pass fp16 GEMM + fused bias/L2norm/leakyrelu ---------
// 512 threads = 16 warps (2m x 8n), tile 64m x 256n, K chunks of 64,
// register-prefetch pipeline; A and B both fp16 in global (pure copies).
#define PADK 72
#define SM_AH   0
#define SM_BH   (SM_AH + 64 * PADK * 2)          //  9216
#define SM_BIAS (SM_BH + 256 * PADK * 2)         // 46080
#define SM_SS   (SM_BIAS + DH * 4)               // 47104
#define SM_INV  (SM_SS + 64 * 8 * 4)             // 49152
#define SM_TOT  (SM_INV + 64 * 4)                // 49408

template <int LAYER>
__global__ void __launch_bounds__(512, 1)
k_gemm_mma(const float* __restrict__ bias) {
    constexpr int K     = (LAYER == 1) ? DIN : DH;
    constexpr int KITER = K / 64;
    extern __shared__ char smem[];
    __half* Ah = (__half*)(smem + SM_AH);
    __half* Bh = (__half*)(smem + SM_BH);
    float* bs  = (float*)(smem + SM_BIAS);
    float* ssb = (float*)(smem + SM_SS);
    float* ivb = (float*)(smem + SM_INV);

    int M = (LAYER == 1) ? NN : g_mcount;
    int m0 = blockIdx.x * 64;
    if (m0 >= M) return;

    int tid = threadIdx.x, wid = tid >> 5, lane = tid & 31;
    int gid = lane >> 2, tig = lane & 3;
    int mw = (wid >> 3) * 32;       // 2 m warp-rows
    int nw = wid & 7;               // 8 n warps
    int nbw = nw * 32;

    if (tid < DH) bs[tid] = bias[tid];

    const __half* A  = (LAYER == 1) ? g_agg1 : g_agg2;
    const __half* Bg = (LAYER == 1) ? g_B1h : g_B2h;

    // A staging: thread -> row tid>>3 (0..63), seg (tid&7)*8 halves (16B)
    int  arl    = tid >> 3;
    int  aseg   = (tid & 7) * 8;
    int  agrow  = m0 + arl;
    bool avalid = agrow < M;
    const __half* arowp = A + (size_t)(avalid ? agrow : 0) * K;
    // B staging: thread -> row tid>>1 (0..255), half (tid&1)*32 halves (4x uint4)
    int brl  = tid >> 1;
    int bseg = (tid & 1) * 32;
    const uint4* bhp = (const uint4*)(Bg + (size_t)brl * K + bseg);

    // ldmatrix lane maps
    uint32_t ah_b = smem_u32(Ah), bh_b = smem_u32(Bh);
    int a_row = mw + (lane & 7) + ((lane >> 3) & 1) * 8;   // + mi*16
    int a_kof = (lane >> 4) * 8;
    int b_row = nbw + (lane & 7) + ((lane >> 4) & 1) * 8;  // + nj*16
    int b_kof = ((lane >> 3) & 1) * 8;

    float acc[2][4][4];
    #pragma unroll
    for (int mi = 0; mi < 2; mi++)
        #pragma unroll
        for (int ni = 0; ni < 4; ni++)
            #pragma unroll
            for (int q = 0; q < 4; q++) acc[mi][ni][q] = 0.f;

    // prefetch registers
    uint4 av, bv[4];
    {
        av = avalid ? *(const uint4*)&arowp[aseg] : make_uint4(0u, 0u, 0u, 0u);
        #pragma unroll
        for (int s = 0; s < 4; s++) bv[s] = __ldg(&bhp[s]);
    }

    for (int it = 0; it < KITER; it++) {
        // ---- store current chunk (regs -> smem) ----
        {
            *(uint4*)&Ah[arl * PADK + aseg] = av;
            int ob = brl * PADK + bseg;
            #pragma unroll
            for (int s = 0; s < 4; s++) *(uint4*)&Bh[ob + s * 8] = bv[s];
        }
        __syncthreads();

        // ---- issue next chunk's global loads (hide under MMA) ----
        if (it + 1 < KITER) {
            int k0n = (it + 1) * 64;
            if (avalid) av = *(const uint4*)&arowp[k0n + aseg];
            const uint4* bhn = bhp + k0n / 8;
            #pragma unroll
            for (int s = 0; s < 4; s++) bv[s] = __ldg(&bhn[s]);
        }

        // ---- MMA: 4 k-steps of 16, ldmatrix fragments ----
        #pragma unroll
        for (int ks = 0; ks < 4; ks++) {
            int kk = ks * 16;
            uint32_t ahf[2][4];
            #pragma unroll
            for (int mi = 0; mi < 2; mi++) {
                uint32_t off = (uint32_t)(((a_row + mi * 16) * PADK + kk + a_kof) * 2);
                ldsm4(ahf[mi], ah_b + off);
            }
            uint32_t bhf[4][2];
            #pragma unroll
            for (int nj = 0; nj < 2; nj++) {
                uint32_t off = (uint32_t)(((b_row + nj * 16) * PADK + kk + b_kof) * 2);
                uint32_t rh[4];
                ldsm4(rh, bh_b + off);
                bhf[2 * nj][0] = rh[0]; bhf[2 * nj][1] = rh[1];
                bhf[2 * nj + 1][0] = rh[2]; bhf[2 * nj + 1][1] = rh[3];
            }
            #pragma unroll
            for (int ni = 0; ni < 4; ni++)
                #pragma unroll
                for (int mi = 0; mi < 2; mi++)
                    mma16816f(acc[mi][ni], ahf[mi], bhf[ni][0], bhf[ni][1]);
        }
        __syncthreads();
    }

    // ---- epilogue: bias, sum-of-squares, normalize, lrelu, store ----
    #pragma unroll
    for (int mi = 0; mi < 2; mi++) {
        #pragma unroll
        for (int rh = 0; rh < 2; rh++) {
            float ss = 0.f;
            #pragma unroll
            for (int ni = 0; ni < 4; ni++) {
                int col = nbw + ni * 8 + 2 * tig;
                float c0 = acc[mi][ni][rh * 2 + 0] + bs[col];
                float c1 = acc[mi][ni][rh * 2 + 1] + bs[col + 1];
                acc[mi][ni][rh * 2 + 0] = c0;
                acc[mi][ni][rh * 2 + 1] = c1;
                ss += c0 * c0 + c1 * c1;
            }
            ss += __shfl_xor_sync(0xffffffffu, ss, 1);
            ss += __shfl_xor_sync(0xffffffffu, ss, 2);
            if (tig == 0) {
                int row = mw + mi * 16 + rh * 8 + gid;
                ssb[row * 8 + nw] = ss;
            }
        }
    }
    __syncthreads();
    if (tid < 64) {
        const float* p = &ssb[tid * 8];
        float s = p[0] + p[1] + p[2] + p[3] + p[4] + p[5] + p[6] + p[7];
        ivb[tid] = 1.f / fmaxf(sqrtf(s), EPSN);
    }
    __syncthreads();

    #pragma unroll
    for (int mi = 0; mi < 2; mi++) {
        #pragma unroll
        for (int rh = 0; rh < 2; rh++) {
            int rl = mw + mi * 16 + rh * 8 + gid;
            int grow = m0 + rl;
            if (grow >= M) continue;
            float inv = ivb[rl];
            if (LAYER == 1) {
                __half* crow = g_h1h + (size_t)grow * DH;
                #pragma unroll
                for (int ni = 0; ni < 4; ni++) {
                    int col = nbw + ni * 8 + 2 * tig;
                    float vx = lrelu(acc[mi][ni][rh * 2 + 0] * inv);
                    float vy = lrelu(acc[mi][ni][rh * 2 + 1] * inv);
                    __half2 hv = __floats2half2_rn(vx, vy);
                    *(__half2*)&crow[col] = hv;
                }
            } else {
                int dst = g_mlist[grow];
                float* crow = g_h2 + (size_t)dst * DH;
                #pragma unroll
                for (int ni = 0; ni < 4; ni++) {
                    int col = nbw + ni * 8 + 2 * tig;
                    float2 v;
                    v.x = lrelu(acc[mi][ni][rh * 2 + 0] * inv);
                    v.y = lrelu(acc[mi][ni][rh * 2 + 1] * inv);
                    *(float2*)&crow[col] = v;
                }
            }
        }
    }
}

// ---------------- layer 3 fused: agg + matvec + normalize ---------------------
__global__ void k_final(const float* __restrict__ W3, const float* __restrict__ b3,
                        float* __restrict__ out) {
    __shared__ float agg[DH];
    __shared__ float red[64];
    int g = blockIdx.x, tid = threadIdx.x;
    int d = g * 100;
    int beg = g_rowptr[d], end = g_rowptr[d + 1];
    float4 acc = make_float4(0.f, 0.f, 0.f, 0.f);
    for (int j = beg; j < end; j++) {
        int s = g_csr[j];
        float4 v = *(const float4*)&g_h2[(size_t)s * DH + tid * 4];
        acc.x += v.x; acc.y += v.y; acc.z += v.z; acc.w += v.w;
    }
    *(float4*)&agg[tid * 4] = acc;
    __syncthreads();
    float o = b3[tid];
    #pragma unroll 8
    for (int k = 0; k < DH; k++) o += agg[k] * W3[k * DOUT + tid];
    red[tid] = o * o;
    __syncthreads();
    #pragma unroll
    for (int s = 32; s > 0; s >>= 1) {
        if (tid < s) red[tid] += red[tid + s];
        __syncthreads();
    }
    float inv = 1.f / fmaxf(sqrtf(red[0]), EPSN);
    out[g * DOUT + tid] = o * inv;
}

// ---------------- launcher ----------------------------------------------------
extern "C" void kernel_launch(void* const* d_in, const int* in_sizes, int n_in,
                              void* d_out, int out_size) {
    const float* x  = (const float*)d_in[0];
    const int*   ei = (const int*)d_in[1];
    const float* W1 = (const float*)d_in[3];
    const float* b1 = (const float*)d_in[4];
    const float* W2 = (const float*)d_in[5];
    const float* b2 = (const float*)d_in[6];
    const float* W3 = (const float*)d_in[7];
    const float* b3 = (const float*)d_in[8];
    float* out = (float*)d_out;

    cudaFuncSetAttribute(k_gemm_mma<1>, cudaFuncAttributeMaxDynamicSharedMemorySize, SM_TOT);
    cudaFuncSetAttribute(k_gemm_mma<2>, cudaFuncAttributeMaxDynamicSharedMemorySize, SM_TOT);

    void *p_deg, *p_mark, *p_mc;
    cudaGetSymbolAddress(&p_deg, g_deg);
    cudaGetSymbolAddress(&p_mark, g_mark);
    cudaGetSymbolAddress(&p_mc, g_mcount);
    cudaMemsetAsync(p_deg, 0, NN * sizeof(int));
    cudaMemsetAsync(p_mark, 0, NN * sizeof(int));
    cudaMemsetAsync(p_mc, 0, sizeof(int));

    const int TB = 256;
    const int nb_prep  = ((NN * DIN / 8) + TB - 1) / TB;   // 3125
    const int nb_edge4 = (NE / 4 + TB - 1) / TB;           // 782
    const int nb_warps = (NN * 32 + TB - 1) / TB;          // 6250
    const int nb_gemm  = (NN + 63) / 64;                   // 782

    k_count_prep<<<nb_prep, TB>>>(ei, x, W1, W2);   // 1
    k_scan1<<<NB, TB>>>();                           // 2
    k_scan23c<<<NB, TB>>>();                         // 3
    k_fill<<<nb_edge4, TB>>>(ei);                    // 4  <- ncu captures this
    k_agg1<<<nb_warps, TB>>>();                      // 5
    k_gemm_mma<1><<<nb_gemm, 512, SM_TOT>>>(b1);     // 6
    k_agg2<<<nb_warps, TB>>>();                      // 7
    k_gemm_mma<2><<<nb_gemm, 512, SM_TOT>>>(b2);     // 8
    k_final<<<NG, DOUT>>>(W3, b3, out);              // 9
}